// round 7
// baseline (speedup 1.0000x reference)
#include <cuda_runtime.h>
#include <cuda_fp16.h>
#include <cstdint>

#define NSP   2304
#define CH    512
#define BATCH 8
#define BK    32
#define PAD   40                       // halves per smem row (16B-aligned, conflict-free)
#define MAT_B (128 * PAD * 2)          // 10240 bytes per matrix tile
#define STG_B (4 * MAT_B)              // Ah, Al, Bh, Bl = 40960 bytes
#define SMEM_TOTAL (2 * STG_B)         // 81920 bytes, double-buffered

// ---------------- scratch (device globals; no allocations) ------------------
__device__ __half g_tT_hi [(size_t)BATCH * NSP * CH];
__device__ __half g_tT_lo [(size_t)BATCH * NSP * CH];
__device__ __half g_iT_hi [(size_t)BATCH * NSP * CH];
__device__ __half g_iT_lo [(size_t)BATCH * NSP * CH];
__device__ __half g_w_hi  [(size_t)4 * CH * CH];
__device__ __half g_w_lo  [(size_t)4 * CH * CH];
__device__ __half g_tfT_hi[(size_t)BATCH * NSP * CH];
__device__ __half g_tfT_lo[(size_t)BATCH * NSP * CH];
__device__ __half g_qT_hi [(size_t)BATCH * NSP * CH];
__device__ __half g_qT_lo [(size_t)BATCH * NSP * CH];
__device__ __half g_kT_hi [(size_t)BATCH * NSP * CH];
__device__ __half g_kT_lo [(size_t)BATCH * NSP * CH];
__device__ __half g_v_hi  [(size_t)BATCH * CH * NSP];
__device__ __half g_v_lo  [(size_t)BATCH * CH * NSP];
__device__ float  g_S     [(size_t)BATCH * NSP * NSP];
__device__ __half g_P_hi  [(size_t)BATCH * NSP * NSP];
__device__ __half g_P_lo  [(size_t)BATCH * NSP * NSP];

// ---------------- helpers ----------------------------------------------------
__device__ __forceinline__ uint32_t smem_u32(const void* p) {
    uint32_t a;
    asm("{ .reg .u64 t; cvta.to.shared.u64 t, %1; cvt.u32.u64 %0, t; }" : "=r"(a) : "l"(p));
    return a;
}
__device__ __forceinline__ void cp16(uint32_t saddr, const void* g) {
    asm volatile("cp.async.cg.shared.global [%0], [%1], 16;\n" :: "r"(saddr), "l"(g));
}
__device__ __forceinline__ void cp_commit() { asm volatile("cp.async.commit_group;\n"); }
template<int N> __device__ __forceinline__ void cp_wait() {
    asm volatile("cp.async.wait_group %0;\n" :: "n"(N));
}
__device__ __forceinline__ void ldsm4(unsigned (&r)[4], uint32_t addr) {
    asm volatile("ldmatrix.sync.aligned.m8n8.x4.shared.b16 {%0,%1,%2,%3}, [%4];"
        : "=r"(r[0]), "=r"(r[1]), "=r"(r[2]), "=r"(r[3]) : "r"(addr));
}
// fp32-accumulate MMA (main hi*hi term)
__device__ __forceinline__ void mma_f32(float (&d)[4], const unsigned (&a)[4],
                                        unsigned b0, unsigned b1) {
    asm volatile(
        "mma.sync.aligned.m16n8k16.row.col.f32.f16.f16.f32 "
        "{%0,%1,%2,%3}, {%4,%5,%6,%7}, {%8,%9}, {%0,%1,%2,%3};\n"
        : "+f"(d[0]), "+f"(d[1]), "+f"(d[2]), "+f"(d[3])
        : "r"(a[0]), "r"(a[1]), "r"(a[2]), "r"(a[3]), "r"(b0), "r"(b1));
}
// f16-accumulate MMA (small correction terms)
__device__ __forceinline__ void mma_f16(unsigned (&d)[2], const unsigned (&a)[4],
                                        unsigned b0, unsigned b1) {
    asm volatile(
        "mma.sync.aligned.m16n8k16.row.col.f16.f16.f16.f16 "
        "{%0,%1}, {%2,%3,%4,%5}, {%6,%7}, {%0,%1};\n"
        : "+r"(d[0]), "+r"(d[1])
        : "r"(a[0]), "r"(a[1]), "r"(a[2]), "r"(a[3]), "r"(b0), "r"(b1));
}
__device__ __forceinline__ void split2(float f, __half& h, __half& l) {
    h = __float2half_rn(f);
    l = __float2half_rn(f - __half2float(h));
}

// ---------------- pre-pass: transpose fp32 [C][N] -> split f16 [N][C] --------
__global__ void split_transpose(const float* __restrict__ in,
                                __half* __restrict__ ohi, __half* __restrict__ olo)
{
    __shared__ float tile[32][33];
    const int bz = blockIdx.z;
    const float* I = in  + (size_t)bz * CH * NSP;
    __half* H = ohi + (size_t)bz * NSP * CH;
    __half* L = olo + (size_t)bz * NSP * CH;
    const int n0 = blockIdx.x * 32, c0 = blockIdx.y * 32;
    const int tx = threadIdx.x, ty = threadIdx.y;
#pragma unroll
    for (int j = 0; j < 32; j += 8)
        tile[ty + j][tx] = I[(size_t)(c0 + ty + j) * NSP + n0 + tx];
    __syncthreads();
#pragma unroll
    for (int j = 0; j < 32; j += 8) {
        float f = tile[tx][ty + j];
        __half h, l; split2(f, h, l);
        size_t off = (size_t)(n0 + ty + j) * CH + c0 + tx;
        H[off] = h; L[off] = l;
    }
}

__global__ void split_w(const float* __restrict__ w0, const float* __restrict__ w1,
                        const float* __restrict__ w2, const float* __restrict__ w3,
                        __half* __restrict__ hi, __half* __restrict__ lo)
{
    const int z = blockIdx.z;
    const float* w = (z == 0) ? w0 : (z == 1) ? w1 : (z == 2) ? w2 : w3;
    const int i = blockIdx.x * 256 + threadIdx.x;
    __half h, l; split2(w[i], h, l);
    hi[(size_t)z * CH * CH + i] = h;
    lo[(size_t)z * CH * CH + i] = l;
}

// ============================================================================
// Split-f16 NT HGEMM: hi*hi -> fp32 acc; (hi*lo + lo*hi) -> f16 acc chain.
//   Y[m][n] = sum_k A[m][k] * B[n][k]   (A,B as hi+lo f16, row stride = K)
// EPI 0: +bias[n] -> split f16 | 1: +bias[m] -> split f16
// EPI 2: *(*aux)  -> fp32      | 3: +res     -> fp32
// ============================================================================
template<int EPI>
__global__ __launch_bounds__(256, 2)
void hgemm_nt(const __half* __restrict__ Agh, const __half* __restrict__ Agl,
              const __half* __restrict__ Bgh, const __half* __restrict__ Bgl,
              const float* __restrict__ aux, const float* __restrict__ resg,
              float* __restrict__ Yfg, __half* __restrict__ Yhg, __half* __restrict__ Ylg,
              int K, int ldY, size_t strA, size_t strB, size_t strY)
{
    extern __shared__ char smem[];
    const uint32_t sb = smem_u32(smem);

    const int bz = blockIdx.z;
    const __half* Ah = Agh + strA * bz;
    const __half* Al = Agl + strA * bz;
    const __half* Bh = Bgh + strB * bz;
    const __half* Bl = Bgl + strB * bz;

    const int n0 = blockIdx.x * 128;
    const int m0 = blockIdx.y * 128;
    const int t    = threadIdx.x;
    const int lane = t & 31;
    const int warp = t >> 5;
    const int wm   = (warp & 3) * 32;
    const int wn   = (warp >> 2) * 64;
    const int grp  = lane >> 2;
    const int qid  = lane & 3;

    // ldmatrix per-lane byte offsets within a matrix tile
    const uint32_t offA = (uint32_t)(wm + (lane & 15)) * (PAD * 2) + (lane >> 4) * 16;
    const uint32_t offB = (uint32_t)(wn + ((lane >> 4) & 1) * 8 + (lane & 7)) * (PAD * 2)
                        + ((lane >> 3) & 1) * 16;

    float acc[2][8][4];
    unsigned corr[2][8][2];
#pragma unroll
    for (int mt = 0; mt < 2; mt++)
#pragma unroll
        for (int nt = 0; nt < 8; nt++) {
#pragma unroll
            for (int r = 0; r < 4; r++) acc[mt][nt][r] = 0.f;
            corr[mt][nt][0] = 0u; corr[mt][nt][1] = 0u;
        }

    auto load_chunk = [&](int c) {
        const int k0 = c * BK;
        const uint32_t so = sb + (c & 1) * STG_B;
        const __half* srcs[4] = { Ah, Al, Bh, Bl };
#pragma unroll
        for (int mat = 0; mat < 4; mat++) {
            const __half* S = srcs[mat];
            const int base = (mat < 2) ? m0 : n0;
#pragma unroll
            for (int i = 0; i < 2; i++) {
                const int idx = t + 256 * i;
                const int kg = idx & 3, r = idx >> 2;
                cp16(so + mat * MAT_B + r * (PAD * 2) + kg * 16,
                     &S[(size_t)(base + r) * K + k0 + kg * 8]);
            }
        }
        cp_commit();
    };

    const int nch = K / BK;
    load_chunk(0);
    load_chunk(1);

    for (int c = 0; c < nch; c++) {
        if (c + 1 < nch) cp_wait<1>(); else cp_wait<0>();
        __syncthreads();

        const uint32_t stg = sb + (c & 1) * STG_B;
        const uint32_t aHb = stg;
        const uint32_t aLb = stg + MAT_B;
        const uint32_t bHb = stg + 2 * MAT_B;
        const uint32_t bLb = stg + 3 * MAT_B;

#pragma unroll
        for (int ks = 0; ks < 2; ks++) {
            const uint32_t kb2 = ks * 32;   // 16 halves = 32 bytes
            unsigned ah[2][4], al[2][4];
            ldsm4(ah[0], aHb + offA + kb2);
            ldsm4(ah[1], aHb + offA + 16 * (PAD * 2) + kb2);
            ldsm4(al[0], aLb + offA + kb2);
            ldsm4(al[1], aLb + offA + 16 * (PAD * 2) + kb2);
#pragma unroll
            for (int np = 0; np < 4; np++) {
                unsigned bh[4], bl[4];
                ldsm4(bh, bHb + offB + np * 16 * (PAD * 2) + kb2);
                ldsm4(bl, bLb + offB + np * 16 * (PAD * 2) + kb2);
                // hi*hi -> fp32 accumulators (full rate of f32-acc pipe)
                mma_f32(acc[0][2 * np],     ah[0], bh[0], bh[1]);
                mma_f32(acc[0][2 * np + 1], ah[0], bh[2], bh[3]);
                mma_f32(acc[1][2 * np],     ah[1], bh[0], bh[1]);
                mma_f32(acc[1][2 * np + 1], ah[1], bh[2], bh[3]);
                // hi*lo -> f16 correction accumulators
                mma_f16(corr[0][2 * np],     ah[0], bl[0], bl[1]);
                mma_f16(corr[0][2 * np + 1], ah[0], bl[2], bl[3]);
                mma_f16(corr[1][2 * np],     ah[1], bl[0], bl[1]);
                mma_f16(corr[1][2 * np + 1], ah[1], bl[2], bl[3]);
                // lo*hi -> same f16 correction accumulators
                mma_f16(corr[0][2 * np],     al[0], bh[0], bh[1]);
                mma_f16(corr[0][2 * np + 1], al[0], bh[2], bh[3]);
                mma_f16(corr[1][2 * np],     al[1], bh[0], bh[1]);
                mma_f16(corr[1][2 * np + 1], al[1], bh[2], bh[3]);
            }
        }
        __syncthreads();
        if (c + 2 < nch) load_chunk(c + 2);
    }

    // ---- epilogue: combine fp32 main + f16 correction ----
    const float* res = (EPI == 3) ? (resg + strY * bz) : nullptr;
    float* Yf  = (EPI >= 2) ? (Yfg + strY * bz) : nullptr;
    __half* Yh = (EPI < 2) ? (Yhg + strY * bz) : nullptr;
    __half* Yl = (EPI < 2) ? (Ylg + strY * bz) : nullptr;
    const float sc = (EPI == 2) ? *aux : 0.f;

#pragma unroll
    for (int mt = 0; mt < 2; mt++)
#pragma unroll
        for (int r2 = 0; r2 < 2; r2++) {
            const int m = m0 + wm + mt * 16 + grp + 8 * r2;
            const float bvr = (EPI == 1) ? aux[m] : 0.f;
#pragma unroll
            for (int nt = 0; nt < 8; nt++) {
                const int n = n0 + wn + nt * 8 + qid * 2;
                const __half2 ch = *reinterpret_cast<const __half2*>(&corr[mt][nt][r2]);
                float v0 = acc[mt][nt][r2 * 2 + 0] + __low2float(ch);
                float v1 = acc[mt][nt][r2 * 2 + 1] + __high2float(ch);
                if (EPI == 0) { v0 += aux[n]; v1 += aux[n + 1]; }
                if (EPI == 1) { v0 += bvr;    v1 += bvr; }
                if (EPI == 2) { v0 *= sc;     v1 *= sc; }
                const size_t off = (size_t)m * ldY + n;
                if (EPI == 3) { v0 += res[off]; v1 += res[off + 1]; }
                if (EPI >= 2) {
                    *(float2*)&Yf[off] = make_float2(v0, v1);
                } else {
                    __half h0, l0, h1, l1;
                    split2(v0, h0, l0); split2(v1, h1, l1);
                    *(__half2*)&Yh[off] = __halves2half2(h0, h1);
                    *(__half2*)&Yl[off] = __halves2half2(l0, l1);
                }
            }
        }
}

// ---------------- softmax over rows of S, emit split-f16 P -------------------
__global__ void softmax_split(const float* __restrict__ S,
                              __half* __restrict__ Ph, __half* __restrict__ Pl)
{
    __shared__ float red[256];
    const size_t ro = (size_t)blockIdx.x * NSP;
    const float* r = S + ro;
    const int t = threadIdx.x;

    float v[9];
    float mx = -1e30f;
#pragma unroll
    for (int i = 0; i < 9; i++) { v[i] = r[t + i * 256]; mx = fmaxf(mx, v[i]); }
    red[t] = mx;
    __syncthreads();
    for (int s = 128; s > 0; s >>= 1) {
        if (t < s) red[t] = fmaxf(red[t], red[t + s]);
        __syncthreads();
    }
    mx = red[0];
    __syncthreads();
    float sum = 0.f;
#pragma unroll
    for (int i = 0; i < 9; i++) { v[i] = __expf(v[i] - mx); sum += v[i]; }
    red[t] = sum;
    __syncthreads();
    for (int s = 128; s > 0; s >>= 1) {
        if (t < s) red[t] += red[t + s];
        __syncthreads();
    }
    const float inv = 1.0f / red[0];
#pragma unroll
    for (int i = 0; i < 9; i++) {
        __half h, l; split2(v[i] * inv, h, l);
        Ph[ro + t + i * 256] = h;
        Pl[ro + t + i * 256] = l;
    }
}

// ============================================================================
// Launch
// ============================================================================
extern "C" void kernel_launch(void* const* d_in, const int* in_sizes, int n_in,
                              void* d_out, int out_size)
{
    const float* img   = (const float*)d_in[0];
    const float* text  = (const float*)d_in[1];
    const float* w_tp  = (const float*)d_in[2];
    const float* b_tp  = (const float*)d_in[3];
    const float* w_q   = (const float*)d_in[4];
    const float* b_q   = (const float*)d_in[5];
    const float* w_k   = (const float*)d_in[6];
    const float* b_k   = (const float*)d_in[7];
    const float* w_v   = (const float*)d_in[8];
    const float* b_v   = (const float*)d_in[9];
    const float* scale = (const float*)d_in[10];

    __half *tTh, *tTl, *iTh, *iTl, *wh, *wl, *tfh, *tfl, *qh, *ql, *kh, *kl, *vh, *vl, *ph, *pl;
    float* sp;
    cudaGetSymbolAddress((void**)&tTh, g_tT_hi);  cudaGetSymbolAddress((void**)&tTl, g_tT_lo);
    cudaGetSymbolAddress((void**)&iTh, g_iT_hi);  cudaGetSymbolAddress((void**)&iTl, g_iT_lo);
    cudaGetSymbolAddress((void**)&wh,  g_w_hi);   cudaGetSymbolAddress((void**)&wl,  g_w_lo);
    cudaGetSymbolAddress((void**)&tfh, g_tfT_hi); cudaGetSymbolAddress((void**)&tfl, g_tfT_lo);
    cudaGetSymbolAddress((void**)&qh,  g_qT_hi);  cudaGetSymbolAddress((void**)&ql,  g_qT_lo);
    cudaGetSymbolAddress((void**)&kh,  g_kT_hi);  cudaGetSymbolAddress((void**)&kl,  g_kT_lo);
    cudaGetSymbolAddress((void**)&vh,  g_v_hi);   cudaGetSymbolAddress((void**)&vl,  g_v_lo);
    cudaGetSymbolAddress((void**)&ph,  g_P_hi);   cudaGetSymbolAddress((void**)&pl,  g_P_lo);
    cudaGetSymbolAddress((void**)&sp,  g_S);

    cudaFuncSetAttribute(hgemm_nt<0>, cudaFuncAttributeMaxDynamicSharedMemorySize, SMEM_TOTAL);
    cudaFuncSetAttribute(hgemm_nt<1>, cudaFuncAttributeMaxDynamicSharedMemorySize, SMEM_TOTAL);
    cudaFuncSetAttribute(hgemm_nt<2>, cudaFuncAttributeMaxDynamicSharedMemorySize, SMEM_TOTAL);
    cudaFuncSetAttribute(hgemm_nt<3>, cudaFuncAttributeMaxDynamicSharedMemorySize, SMEM_TOTAL);

    const size_t sNC = (size_t)NSP * CH;
    const size_t sNN = (size_t)NSP * NSP;
    const size_t sW  = (size_t)CH * CH;

    dim3 tb(32, 8);
    dim3 tg(NSP / 32, CH / 32, BATCH);
    split_transpose<<<tg, tb>>>(text, tTh, tTl);
    split_transpose<<<tg, tb>>>(img,  iTh, iTl);
    split_w<<<dim3(CH * CH / 256, 1, 4), 256>>>(w_tp, w_q, w_k, w_v, wh, wl);

    dim3 blk(256);
    dim3 grid_p (CH / 128, NSP / 128, BATCH);   // M=NSP, N=CH
    dim3 grid_v (NSP / 128, CH / 128, BATCH);   // M=CH,  N=NSP
    dim3 grid_s (NSP / 128, NSP / 128, BATCH);  // M=NSP, N=NSP

    // tfT[n][o] = text^T @ w_tp^T + b_tp
    hgemm_nt<0><<<grid_p, blk, SMEM_TOTAL>>>(tTh, tTl, wh, wl, b_tp, nullptr,
                                             nullptr, tfh, tfl, CH, CH, sNC, 0, sNC);
    // QT[n][o] = img^T @ w_q^T + b_q
    hgemm_nt<0><<<grid_p, blk, SMEM_TOTAL>>>(iTh, iTl, wh + sW, wl + sW, b_q, nullptr,
                                             nullptr, qh, ql, CH, CH, sNC, 0, sNC);
    // KT[n][o] = tfT @ w_k^T + b_k
    hgemm_nt<0><<<grid_p, blk, SMEM_TOTAL>>>(tfh, tfl, wh + 2 * sW, wl + 2 * sW, b_k, nullptr,
                                             nullptr, kh, kl, CH, CH, sNC, 0, sNC);
    // V[o][n] = w_v @ tf + b_v
    hgemm_nt<1><<<grid_v, blk, SMEM_TOTAL>>>(wh + 3 * sW, wl + 3 * sW, tfh, tfl, b_v, nullptr,
                                             nullptr, vh, vl, CH, NSP, 0, sNC, sNC);
    // S = scale * QT @ KT^T
    hgemm_nt<2><<<grid_s, blk, SMEM_TOTAL>>>(qh, ql, kh, kl, scale, nullptr,
                                             sp, nullptr, nullptr, CH, NSP, sNC, sNC, sNN);
    // P = softmax(S)
    softmax_split<<<BATCH * NSP, 256>>>(sp, ph, pl);
    // out = V @ P^T + img
    hgemm_nt<3><<<grid_v, blk, SMEM_TOTAL>>>(vh, vl, ph, pl, nullptr, img,
                                             (float*)d_out, nullptr, nullptr,
                                             NSP, NSP, sNC, sNN, sNC);
}

// round 8
// speedup vs baseline: 1.3297x; 1.3297x over previous
#include <cuda_runtime.h>
#include <cuda_fp16.h>
#include <cstdint>

#define NSP   2304
#define CH    512
#define BATCH 8
#define BK    32
#define PAD   40                       // halves per smem row (split kernel)
#define MAT_B (128 * PAD * 2)          // 10240 bytes per matrix tile
#define STG_B (4 * MAT_B)              // Ah, Al, Bh, Bl = 40960 bytes
#define SMEM_TOTAL (2 * STG_B)         // 81920 bytes, double-buffered

// ---- pure-f16 out-GEMM kernel params (BK=64) ----
#define BK2    64
#define PAD2   72                      // 64 + 8 halves; stride 144B, conflict-free
#define MAT2_B (128 * PAD2 * 2)        // 18432 bytes
#define STG2_B (2 * MAT2_B)            // A, B = 36864 bytes
#define SMEM2_TOTAL (2 * STG2_B)       // 73728 bytes

// ---------------- scratch (device globals; no allocations) ------------------
__device__ __half g_tT_hi [(size_t)BATCH * NSP * CH];
__device__ __half g_tT_lo [(size_t)BATCH * NSP * CH];
__device__ __half g_iT_hi [(size_t)BATCH * NSP * CH];
__device__ __half g_iT_lo [(size_t)BATCH * NSP * CH];
__device__ __half g_w_hi  [(size_t)4 * CH * CH];
__device__ __half g_w_lo  [(size_t)4 * CH * CH];
__device__ __half g_tfT_hi[(size_t)BATCH * NSP * CH];
__device__ __half g_tfT_lo[(size_t)BATCH * NSP * CH];
__device__ __half g_qT_hi [(size_t)BATCH * NSP * CH];
__device__ __half g_qT_lo [(size_t)BATCH * NSP * CH];
__device__ __half g_kT_hi [(size_t)BATCH * NSP * CH];
__device__ __half g_kT_lo [(size_t)BATCH * NSP * CH];
__device__ __half g_v_hi  [(size_t)BATCH * CH * NSP];
__device__ __half g_v_lo  [(size_t)BATCH * CH * NSP];
__device__ float  g_S     [(size_t)BATCH * NSP * NSP];
__device__ __half g_P_hi  [(size_t)BATCH * NSP * NSP];

// ---------------- helpers ----------------------------------------------------
__device__ __forceinline__ uint32_t smem_u32(const void* p) {
    uint32_t a;
    asm("{ .reg .u64 t; cvta.to.shared.u64 t, %1; cvt.u32.u64 %0, t; }" : "=r"(a) : "l"(p));
    return a;
}
__device__ __forceinline__ void cp16(uint32_t saddr, const void* g) {
    asm volatile("cp.async.cg.shared.global [%0], [%1], 16;\n" :: "r"(saddr), "l"(g));
}
__device__ __forceinline__ void cp_commit() { asm volatile("cp.async.commit_group;\n"); }
template<int N> __device__ __forceinline__ void cp_wait() {
    asm volatile("cp.async.wait_group %0;\n" :: "n"(N));
}
__device__ __forceinline__ void ldsm4(unsigned (&r)[4], uint32_t addr) {
    asm volatile("ldmatrix.sync.aligned.m8n8.x4.shared.b16 {%0,%1,%2,%3}, [%4];"
        : "=r"(r[0]), "=r"(r[1]), "=r"(r[2]), "=r"(r[3]) : "r"(addr));
}
__device__ __forceinline__ void mma16816(float (&d)[4], const unsigned (&a)[4],
                                         unsigned b0, unsigned b1) {
    asm volatile(
        "mma.sync.aligned.m16n8k16.row.col.f32.f16.f16.f32 "
        "{%0,%1,%2,%3}, {%4,%5,%6,%7}, {%8,%9}, {%0,%1,%2,%3};\n"
        : "+f"(d[0]), "+f"(d[1]), "+f"(d[2]), "+f"(d[3])
        : "r"(a[0]), "r"(a[1]), "r"(a[2]), "r"(a[3]), "r"(b0), "r"(b1));
}
__device__ __forceinline__ void split2(float f, __half& h, __half& l) {
    h = __float2half_rn(f);
    l = __float2half_rn(f - __half2float(h));
}

// ---------------- pre-pass: transpose fp32 [C][N] -> split f16 [N][C] --------
__global__ void split_transpose(const float* __restrict__ in,
                                __half* __restrict__ ohi, __half* __restrict__ olo)
{
    __shared__ float tile[32][33];
    const int bz = blockIdx.z;
    const float* I = in  + (size_t)bz * CH * NSP;
    __half* H = ohi + (size_t)bz * NSP * CH;
    __half* L = olo + (size_t)bz * NSP * CH;
    const int n0 = blockIdx.x * 32, c0 = blockIdx.y * 32;
    const int tx = threadIdx.x, ty = threadIdx.y;
#pragma unroll
    for (int j = 0; j < 32; j += 8)
        tile[ty + j][tx] = I[(size_t)(c0 + ty + j) * NSP + n0 + tx];
    __syncthreads();
#pragma unroll
    for (int j = 0; j < 32; j += 8) {
        float f = tile[tx][ty + j];
        __half h, l; split2(f, h, l);
        size_t off = (size_t)(n0 + ty + j) * CH + c0 + tx;
        H[off] = h; L[off] = l;
    }
}

__global__ void split_w(const float* __restrict__ w0, const float* __restrict__ w1,
                        const float* __restrict__ w2, const float* __restrict__ w3,
                        __half* __restrict__ hi, __half* __restrict__ lo)
{
    const int z = blockIdx.z;
    const float* w = (z == 0) ? w0 : (z == 1) ? w1 : (z == 2) ? w2 : w3;
    const int i = blockIdx.x * 256 + threadIdx.x;
    __half h, l; split2(w[i], h, l);
    hi[(size_t)z * CH * CH + i] = h;
    lo[(size_t)z * CH * CH + i] = l;
}

// ============================================================================
// Split-f16 NT HGEMM (R6 mainloop): 3 f32-acc mma passes per fragment set.
// EPI 0: +bias[n] -> split f16 | 1: +bias[m] -> split f16 | 2: *(*aux) -> fp32
// ============================================================================
template<int EPI>
__global__ __launch_bounds__(256, 2)
void hgemm_nt(const __half* __restrict__ Agh, const __half* __restrict__ Agl,
              const __half* __restrict__ Bgh, const __half* __restrict__ Bgl,
              const float* __restrict__ aux,
              float* __restrict__ Yfg, __half* __restrict__ Yhg, __half* __restrict__ Ylg,
              int K, int ldY, size_t strA, size_t strB, size_t strY)
{
    extern __shared__ char smem[];
    const uint32_t sb = smem_u32(smem);

    const int bz = blockIdx.z;
    const __half* Ah = Agh + strA * bz;
    const __half* Al = Agl + strA * bz;
    const __half* Bh = Bgh + strB * bz;
    const __half* Bl = Bgl + strB * bz;

    const int n0 = blockIdx.x * 128;
    const int m0 = blockIdx.y * 128;
    const int t    = threadIdx.x;
    const int lane = t & 31;
    const int warp = t >> 5;
    const int wm   = (warp & 3) * 32;
    const int wn   = (warp >> 2) * 64;
    const int grp  = lane >> 2;
    const int qid  = lane & 3;

    const uint32_t offA = (uint32_t)(wm + (lane & 15)) * (PAD * 2) + (lane >> 4) * 16;
    const uint32_t offB = (uint32_t)(wn + ((lane >> 4) & 1) * 8 + (lane & 7)) * (PAD * 2)
                        + ((lane >> 3) & 1) * 16;

    float acc[2][8][4];
#pragma unroll
    for (int mt = 0; mt < 2; mt++)
#pragma unroll
        for (int nt = 0; nt < 8; nt++)
#pragma unroll
            for (int r = 0; r < 4; r++) acc[mt][nt][r] = 0.f;

    auto load_chunk = [&](int c) {
        const int k0 = c * BK;
        const uint32_t so = sb + (c & 1) * STG_B;
        const __half* srcs[4] = { Ah, Al, Bh, Bl };
#pragma unroll
        for (int mat = 0; mat < 4; mat++) {
            const __half* S = srcs[mat];
            const int base = (mat < 2) ? m0 : n0;
#pragma unroll
            for (int i = 0; i < 2; i++) {
                const int idx = t + 256 * i;
                const int kg = idx & 3, r = idx >> 2;
                cp16(so + mat * MAT_B + r * (PAD * 2) + kg * 16,
                     &S[(size_t)(base + r) * K + k0 + kg * 8]);
            }
        }
        cp_commit();
    };

    const int nch = K / BK;
    load_chunk(0);
    load_chunk(1);

    for (int c = 0; c < nch; c++) {
        if (c + 1 < nch) cp_wait<1>(); else cp_wait<0>();
        __syncthreads();

        const uint32_t stg = sb + (c & 1) * STG_B;
        const uint32_t aHb = stg;
        const uint32_t aLb = stg + MAT_B;
        const uint32_t bHb = stg + 2 * MAT_B;
        const uint32_t bLb = stg + 3 * MAT_B;

#pragma unroll
        for (int ks = 0; ks < 2; ks++) {
            const uint32_t kb2 = ks * 32;
            unsigned ah[2][4], al[2][4];
            ldsm4(ah[0], aHb + offA + kb2);
            ldsm4(ah[1], aHb + offA + 16 * (PAD * 2) + kb2);
            ldsm4(al[0], aLb + offA + kb2);
            ldsm4(al[1], aLb + offA + 16 * (PAD * 2) + kb2);
#pragma unroll
            for (int np = 0; np < 4; np++) {
                unsigned bh[4], bl[4];
                ldsm4(bh, bHb + offB + np * 16 * (PAD * 2) + kb2);
                ldsm4(bl, bLb + offB + np * 16 * (PAD * 2) + kb2);
                mma16816(acc[0][2 * np],     ah[0], bh[0], bh[1]);
                mma16816(acc[0][2 * np + 1], ah[0], bh[2], bh[3]);
                mma16816(acc[1][2 * np],     ah[1], bh[0], bh[1]);
                mma16816(acc[1][2 * np + 1], ah[1], bh[2], bh[3]);
                mma16816(acc[0][2 * np],     ah[0], bl[0], bl[1]);
                mma16816(acc[0][2 * np + 1], ah[0], bl[2], bl[3]);
                mma16816(acc[1][2 * np],     ah[1], bl[0], bl[1]);
                mma16816(acc[1][2 * np + 1], ah[1], bl[2], bl[3]);
                mma16816(acc[0][2 * np],     al[0], bh[0], bh[1]);
                mma16816(acc[0][2 * np + 1], al[0], bh[2], bh[3]);
                mma16816(acc[1][2 * np],     al[1], bh[0], bh[1]);
                mma16816(acc[1][2 * np + 1], al[1], bh[2], bh[3]);
            }
        }
        __syncthreads();
        if (c + 2 < nch) load_chunk(c + 2);
    }

    float* Yf  = (EPI == 2) ? (Yfg + strY * bz) : nullptr;
    __half* Yh = (EPI < 2) ? (Yhg + strY * bz) : nullptr;
    __half* Yl = (EPI < 2) ? (Ylg + strY * bz) : nullptr;
    const float sc = (EPI == 2) ? *aux : 0.f;

#pragma unroll
    for (int mt = 0; mt < 2; mt++)
#pragma unroll
        for (int r2 = 0; r2 < 2; r2++) {
            const int m = m0 + wm + mt * 16 + grp + 8 * r2;
            const float bvr = (EPI == 1) ? aux[m] : 0.f;
#pragma unroll
            for (int nt = 0; nt < 8; nt++) {
                const int n = n0 + wn + nt * 8 + qid * 2;
                float v0 = acc[mt][nt][r2 * 2 + 0];
                float v1 = acc[mt][nt][r2 * 2 + 1];
                if (EPI == 0) { v0 += aux[n]; v1 += aux[n + 1]; }
                if (EPI == 1) { v0 += bvr;    v1 += bvr; }
                if (EPI == 2) { v0 *= sc;     v1 *= sc; }
                const size_t off = (size_t)m * ldY + n;
                if (EPI == 2) {
                    *(float2*)&Yf[off] = make_float2(v0, v1);
                } else {
                    __half h0, l0, h1, l1;
                    split2(v0, h0, l0); split2(v1, h1, l1);
                    *(__half2*)&Yh[off] = __halves2half2(h0, h1);
                    *(__half2*)&Yl[off] = __halves2half2(l0, l1);
                }
            }
        }
}

// ============================================================================
// Pure-f16 NT HGEMM (single mma pass, BK=64): out = A @ B^T + res.
// A = V_hi [CH][NSP-k], B = P_hi [NSP][NSP-k], fp32 accum, fp32 out.
// ============================================================================
__global__ __launch_bounds__(256, 2)
void hgemm_f16(const __half* __restrict__ Ag, const __half* __restrict__ Bg,
               const float* __restrict__ resg, float* __restrict__ Yg,
               int K, int ldY, size_t strA, size_t strB, size_t strY)
{
    extern __shared__ char smem[];
    const uint32_t sb = smem_u32(smem);

    const int bz = blockIdx.z;
    const __half* A = Ag + strA * bz;
    const __half* B = Bg + strB * bz;
    const float* res = resg + strY * bz;
    float* Y = Yg + strY * bz;

    const int n0 = blockIdx.x * 128;
    const int m0 = blockIdx.y * 128;
    const int t    = threadIdx.x;
    const int lane = t & 31;
    const int warp = t >> 5;
    const int wm   = (warp & 3) * 32;
    const int wn   = (warp >> 2) * 64;
    const int grp  = lane >> 2;
    const int qid  = lane & 3;

    const uint32_t offA = (uint32_t)(wm + (lane & 15)) * (PAD2 * 2) + (lane >> 4) * 16;
    const uint32_t offB = (uint32_t)(wn + ((lane >> 4) & 1) * 8 + (lane & 7)) * (PAD2 * 2)
                        + ((lane >> 3) & 1) * 16;

    float acc[2][8][4];
#pragma unroll
    for (int mt = 0; mt < 2; mt++)
#pragma unroll
        for (int nt = 0; nt < 8; nt++)
#pragma unroll
            for (int r = 0; r < 4; r++) acc[mt][nt][r] = 0.f;

    auto load_chunk = [&](int c) {
        const int k0 = c * BK2;
        const uint32_t so = sb + (c & 1) * STG2_B;
#pragma unroll
        for (int i = 0; i < 4; i++) {           // A: 128 rows x 8 chunks of 16B
            const int idx = t + 256 * i;
            const int kg = idx & 7, r = idx >> 3;
            cp16(so + r * (PAD2 * 2) + kg * 16,
                 &A[(size_t)(m0 + r) * K + k0 + kg * 8]);
        }
#pragma unroll
        for (int i = 0; i < 4; i++) {           // B
            const int idx = t + 256 * i;
            const int kg = idx & 7, r = idx >> 3;
            cp16(so + MAT2_B + r * (PAD2 * 2) + kg * 16,
                 &B[(size_t)(n0 + r) * K + k0 + kg * 8]);
        }
        cp_commit();
    };

    const int nch = K / BK2;
    load_chunk(0);
    load_chunk(1);

    for (int c = 0; c < nch; c++) {
        if (c + 1 < nch) cp_wait<1>(); else cp_wait<0>();
        __syncthreads();

        const uint32_t stg = sb + (c & 1) * STG2_B;
        const uint32_t aB = stg;
        const uint32_t bB = stg + MAT2_B;

#pragma unroll
        for (int ks = 0; ks < 4; ks++) {
            const uint32_t kb2 = ks * 32;       // 16 halves = 32 bytes
            unsigned a[2][4];
            ldsm4(a[0], aB + offA + kb2);
            ldsm4(a[1], aB + offA + 16 * (PAD2 * 2) + kb2);
#pragma unroll
            for (int np = 0; np < 4; np++) {
                unsigned b[4];
                ldsm4(b, bB + offB + np * 16 * (PAD2 * 2) + kb2);
                mma16816(acc[0][2 * np],     a[0], b[0], b[1]);
                mma16816(acc[0][2 * np + 1], a[0], b[2], b[3]);
                mma16816(acc[1][2 * np],     a[1], b[0], b[1]);
                mma16816(acc[1][2 * np + 1], a[1], b[2], b[3]);
            }
        }
        __syncthreads();
        if (c + 2 < nch) load_chunk(c + 2);
    }

#pragma unroll
    for (int mt = 0; mt < 2; mt++)
#pragma unroll
        for (int r2 = 0; r2 < 2; r2++) {
            const int m = m0 + wm + mt * 16 + grp + 8 * r2;
#pragma unroll
            for (int nt = 0; nt < 8; nt++) {
                const int n = n0 + wn + nt * 8 + qid * 2;
                const size_t off = (size_t)m * ldY + n;
                float v0 = acc[mt][nt][r2 * 2 + 0] + res[off];
                float v1 = acc[mt][nt][r2 * 2 + 1] + res[off + 1];
                *(float2*)&Y[off] = make_float2(v0, v1);
            }
        }
}

// ---------------- softmax over rows of S, emit f16 P (hi only) ---------------
__global__ void softmax_f16(const float* __restrict__ S, __half* __restrict__ Ph)
{
    __shared__ float red[256];
    const size_t ro = (size_t)blockIdx.x * NSP;
    const float* r = S + ro;
    const int t = threadIdx.x;

    float v[9];
    float mx = -1e30f;
#pragma unroll
    for (int i = 0; i < 9; i++) { v[i] = r[t + i * 256]; mx = fmaxf(mx, v[i]); }
    red[t] = mx;
    __syncthreads();
    for (int s = 128; s > 0; s >>= 1) {
        if (t < s) red[t] = fmaxf(red[t], red[t + s]);
        __syncthreads();
    }
    mx = red[0];
    __syncthreads();
    float sum = 0.f;
#pragma unroll
    for (int i = 0; i < 9; i++) { v[i] = __expf(v[i] - mx); sum += v[i]; }
    red[t] = sum;
    __syncthreads();
    for (int s = 128; s > 0; s >>= 1) {
        if (t < s) red[t] += red[t + s];
        __syncthreads();
    }
    const float inv = 1.0f / red[0];
#pragma unroll
    for (int i = 0; i < 9; i++)
        Ph[ro + t + i * 256] = __float2half_rn(v[i] * inv);
}

// ============================================================================
// Launch
// ============================================================================
extern "C" void kernel_launch(void* const* d_in, const int* in_sizes, int n_in,
                              void* d_out, int out_size)
{
    const float* img   = (const float*)d_in[0];
    const float* text  = (const float*)d_in[1];
    const float* w_tp  = (const float*)d_in[2];
    const float* b_tp  = (const float*)d_in[3];
    const float* w_q   = (const float*)d_in[4];
    const float* b_q   = (const float*)d_in[5];
    const float* w_k   = (const float*)d_in[6];
    const float* b_k   = (const float*)d_in[7];
    const float* w_v   = (const float*)d_in[8];
    const float* b_v   = (const float*)d_in[9];
    const float* scale = (const float*)d_in[10];

    __half *tTh, *tTl, *iTh, *iTl, *wh, *wl, *tfh, *tfl, *qh, *ql, *kh, *kl, *vh, *vl, *ph;
    float* sp;
    cudaGetSymbolAddress((void**)&tTh, g_tT_hi);  cudaGetSymbolAddress((void**)&tTl, g_tT_lo);
    cudaGetSymbolAddress((void**)&iTh, g_iT_hi);  cudaGetSymbolAddress((void**)&iTl, g_iT_lo);
    cudaGetSymbolAddress((void**)&wh,  g_w_hi);   cudaGetSymbolAddress((void**)&wl,  g_w_lo);
    cudaGetSymbolAddress((void**)&tfh, g_tfT_hi); cudaGetSymbolAddress((void**)&tfl, g_tfT_lo);
    cudaGetSymbolAddress((void**)&qh,  g_qT_hi);  cudaGetSymbolAddress((void**)&ql,  g_qT_lo);
    cudaGetSymbolAddress((void**)&kh,  g_kT_hi);  cudaGetSymbolAddress((void**)&kl,  g_kT_lo);
    cudaGetSymbolAddress((void**)&vh,  g_v_hi);   cudaGetSymbolAddress((void**)&vl,  g_v_lo);
    cudaGetSymbolAddress((void**)&ph,  g_P_hi);
    cudaGetSymbolAddress((void**)&sp,  g_S);

    cudaFuncSetAttribute(hgemm_nt<0>, cudaFuncAttributeMaxDynamicSharedMemorySize, SMEM_TOTAL);
    cudaFuncSetAttribute(hgemm_nt<1>, cudaFuncAttributeMaxDynamicSharedMemorySize, SMEM_TOTAL);
    cudaFuncSetAttribute(hgemm_nt<2>, cudaFuncAttributeMaxDynamicSharedMemorySize, SMEM_TOTAL);
    cudaFuncSetAttribute(hgemm_f16,   cudaFuncAttributeMaxDynamicSharedMemorySize, SMEM2_TOTAL);

    const size_t sNC = (size_t)NSP * CH;
    const size_t sNN = (size_t)NSP * NSP;
    const size_t sW  = (size_t)CH * CH;

    dim3 tb(32, 8);
    dim3 tg(NSP / 32, CH / 32, BATCH);
    split_transpose<<<tg, tb>>>(text, tTh, tTl);
    split_transpose<<<tg, tb>>>(img,  iTh, iTl);
    split_w<<<dim3(CH * CH / 256, 1, 4), 256>>>(w_tp, w_q, w_k, w_v, wh, wl);

    dim3 blk(256);
    dim3 grid_p (CH / 128, NSP / 128, BATCH);   // M=NSP, N=CH
    dim3 grid_v (NSP / 128, CH / 128, BATCH);   // M=CH,  N=NSP
    dim3 grid_s (NSP / 128, NSP / 128, BATCH);  // M=NSP, N=NSP

    // tfT[n][o] = text^T @ w_tp^T + b_tp
    hgemm_nt<0><<<grid_p, blk, SMEM_TOTAL>>>(tTh, tTl, wh, wl, b_tp,
                                             nullptr, tfh, tfl, CH, CH, sNC, 0, sNC);
    // QT[n][o] = img^T @ w_q^T + b_q
    hgemm_nt<0><<<grid_p, blk, SMEM_TOTAL>>>(iTh, iTl, wh + sW, wl + sW, b_q,
                                             nullptr, qh, ql, CH, CH, sNC, 0, sNC);
    // KT[n][o] = tfT @ w_k^T + b_k
    hgemm_nt<0><<<grid_p, blk, SMEM_TOTAL>>>(tfh, tfl, wh + 2 * sW, wl + 2 * sW, b_k,
                                             nullptr, kh, kl, CH, CH, sNC, 0, sNC);
    // V[o][n] = w_v @ tf + b_v
    hgemm_nt<1><<<grid_v, blk, SMEM_TOTAL>>>(wh + 3 * sW, wl + 3 * sW, tfh, tfl, b_v,
                                             nullptr, vh, vl, CH, NSP, 0, sNC, sNC);
    // S = scale * QT @ KT^T
    hgemm_nt<2><<<grid_s, blk, SMEM_TOTAL>>>(qh, ql, kh, kl, scale,
                                             sp, nullptr, nullptr, CH, NSP, sNC, sNC, sNN);
    // P = softmax(S), f16
    softmax_f16<<<BATCH * NSP, 256>>>(sp, ph);
    // out = V_hi @ P^T + img   (pure f16, single pass)
    hgemm_f16<<<grid_v, blk, SMEM2_TOTAL>>>(vh, ph, img, (float*)d_out,
                                            NSP, NSP, sNC, sNN, sNC);
}

// round 9
// speedup vs baseline: 1.5562x; 1.1703x over previous
#include <cuda_runtime.h>
#include <cuda_fp16.h>
#include <cstdint>

#define NSP   2304
#define CH    512
#define BATCH 8
#define BK    32
#define PAD   40                       // halves per smem row (16B-aligned, conflict-free)
#define MAT_B (128 * PAD * 2)          // 10240 bytes per matrix tile

// ---- pure-f16 out-GEMM kernel params (BK=64) ----
#define BK2    64
#define PAD2   72
#define MAT2_B (128 * PAD2 * 2)        // 18432 bytes
#define STG2_B (2 * MAT2_B)
#define SMEM2_TOTAL (2 * STG2_B)       // 73728 bytes

// ---------------- scratch (device globals; no allocations) ------------------
__device__ __half g_tT_hi [(size_t)BATCH * NSP * CH];
__device__ __half g_tT_lo [(size_t)BATCH * NSP * CH];
__device__ __half g_iT_hi [(size_t)BATCH * NSP * CH];
__device__ __half g_iT_lo [(size_t)BATCH * NSP * CH];
__device__ __half g_w_hi  [(size_t)4 * CH * CH];
__device__ __half g_w_lo  [(size_t)4 * CH * CH];
__device__ __half g_tfT_hi[(size_t)BATCH * NSP * CH];
__device__ __half g_tfT_lo[(size_t)BATCH * NSP * CH];
__device__ __half g_qT_hi [(size_t)BATCH * NSP * CH];
__device__ __half g_kT_hi [(size_t)BATCH * NSP * CH];
__device__ __half g_kT_lo [(size_t)BATCH * NSP * CH];
__device__ __half g_v_hi  [(size_t)BATCH * CH * NSP];
__device__ float  g_S     [(size_t)BATCH * NSP * NSP];
__device__ __half g_P_hi  [(size_t)BATCH * NSP * NSP];

// ---------------- helpers ----------------------------------------------------
__device__ __forceinline__ uint32_t smem_u32(const void* p) {
    uint32_t a;
    asm("{ .reg .u64 t; cvta.to.shared.u64 t, %1; cvt.u32.u64 %0, t; }" : "=r"(a) : "l"(p));
    return a;
}
__device__ __forceinline__ void cp16(uint32_t saddr, const void* g) {
    asm volatile("cp.async.cg.shared.global [%0], [%1], 16;\n" :: "r"(saddr), "l"(g));
}
__device__ __forceinline__ void cp_commit() { asm volatile("cp.async.commit_group;\n"); }
template<int N> __device__ __forceinline__ void cp_wait() {
    asm volatile("cp.async.wait_group %0;\n" :: "n"(N));
}
__device__ __forceinline__ void ldsm4(unsigned (&r)[4], uint32_t addr) {
    asm volatile("ldmatrix.sync.aligned.m8n8.x4.shared.b16 {%0,%1,%2,%3}, [%4];"
        : "=r"(r[0]), "=r"(r[1]), "=r"(r[2]), "=r"(r[3]) : "r"(addr));
}
__device__ __forceinline__ void mma16816(float (&d)[4], const unsigned (&a)[4],
                                         unsigned b0, unsigned b1) {
    asm volatile(
        "mma.sync.aligned.m16n8k16.row.col.f32.f16.f16.f32 "
        "{%0,%1,%2,%3}, {%4,%5,%6,%7}, {%8,%9}, {%0,%1,%2,%3};\n"
        : "+f"(d[0]), "+f"(d[1]), "+f"(d[2]), "+f"(d[3])
        : "r"(a[0]), "r"(a[1]), "r"(a[2]), "r"(a[3]), "r"(b0), "r"(b1));
}
__device__ __forceinline__ void split2(float f, __half& h, __half& l) {
    h = __float2half_rn(f);
    l = __float2half_rn(f - __half2float(h));
}

// ---------------- pre-pass: transpose fp32 [C][N] -> split f16 [N][C] --------
__global__ void split_transpose(const float* __restrict__ in,
                                __half* __restrict__ ohi, __half* __restrict__ olo)
{
    __shared__ float tile[32][33];
    const int bz = blockIdx.z;
    const float* I = in  + (size_t)bz * CH * NSP;
    __half* H = ohi + (size_t)bz * NSP * CH;
    __half* L = olo + (size_t)bz * NSP * CH;
    const int n0 = blockIdx.x * 32, c0 = blockIdx.y * 32;
    const int tx = threadIdx.x, ty = threadIdx.y;
#pragma unroll
    for (int j = 0; j < 32; j += 8)
        tile[ty + j][tx] = I[(size_t)(c0 + ty + j) * NSP + n0 + tx];
    __syncthreads();
#pragma unroll
    for (int j = 0; j < 32; j += 8) {
        float f = tile[tx][ty + j];
        __half h, l; split2(f, h, l);
        size_t off = (size_t)(n0 + ty + j) * CH + c0 + tx;
        H[off] = h; L[off] = l;
    }
}

__global__ void split_w(const float* __restrict__ w0, const float* __restrict__ w1,
                        const float* __restrict__ w2, const float* __restrict__ w3,
                        __half* __restrict__ hi, __half* __restrict__ lo)
{
    const int z = blockIdx.z;
    const float* w = (z == 0) ? w0 : (z == 1) ? w1 : (z == 2) ? w2 : w3;
    const int i = blockIdx.x * 256 + threadIdx.x;
    __half h, l; split2(w[i], h, l);
    hi[(size_t)z * CH * CH + i] = h;
    lo[(size_t)z * CH * CH + i] = l;
}

// ============================================================================
// Unified split-f16 NT HGEMM.  Y[m][n] = sum_k A[m][k]*B[n][k]
// Passes: hi*hi always; + ah*bl if UBL; + al*bh if UAL.
// EPI 0: +bias[n] -> split f16 | 1: +bias[n] -> hi f16
// EPI 2: +bias[m] -> hi f16    | 3: *(*aux)  -> fp32
// ============================================================================
template<bool UAL, bool UBL, int EPI>
__global__ __launch_bounds__(256, 2)
void hgemm_nt(const __half* __restrict__ Agh, const __half* __restrict__ Agl,
              const __half* __restrict__ Bgh, const __half* __restrict__ Bgl,
              const float* __restrict__ aux,
              float* __restrict__ Yfg, __half* __restrict__ Yhg, __half* __restrict__ Ylg,
              int K, int ldY, size_t strA, size_t strB, size_t strY)
{
    constexpr int NMAT  = 2 + (UAL ? 1 : 0) + (UBL ? 1 : 0);
    constexpr int STGB  = NMAT * MAT_B;
    constexpr uint32_t OFF_AH = 0;
    constexpr uint32_t OFF_BH = MAT_B;
    constexpr uint32_t OFF_BL = 2 * MAT_B;                       // valid if UBL
    constexpr uint32_t OFF_AL = (2 + (UBL ? 1 : 0)) * MAT_B;     // valid if UAL

    extern __shared__ char smem[];
    const uint32_t sb = smem_u32(smem);

    const int bz = blockIdx.z;
    const __half* Ah = Agh + strA * bz;
    const __half* Al = UAL ? (Agl + strA * bz) : nullptr;
    const __half* Bh = Bgh + strB * bz;
    const __half* Bl = UBL ? (Bgl + strB * bz) : nullptr;

    const int n0 = blockIdx.x * 128;
    const int m0 = blockIdx.y * 128;
    const int t    = threadIdx.x;
    const int lane = t & 31;
    const int warp = t >> 5;
    const int wm   = (warp & 3) * 32;
    const int wn   = (warp >> 2) * 64;
    const int grp  = lane >> 2;
    const int qid  = lane & 3;

    const uint32_t offA = (uint32_t)(wm + (lane & 15)) * (PAD * 2) + (lane >> 4) * 16;
    const uint32_t offB = (uint32_t)(wn + ((lane >> 4) & 1) * 8 + (lane & 7)) * (PAD * 2)
                        + ((lane >> 3) & 1) * 16;

    float acc[2][8][4];
#pragma unroll
    for (int mt = 0; mt < 2; mt++)
#pragma unroll
        for (int nt = 0; nt < 8; nt++)
#pragma unroll
            for (int r = 0; r < 4; r++) acc[mt][nt][r] = 0.f;

    auto load_mat = [&](const __half* S, int base, uint32_t moff, int k0, uint32_t so) {
#pragma unroll
        for (int i = 0; i < 2; i++) {
            const int idx = t + 256 * i;
            const int kg = idx & 3, r = idx >> 2;
            cp16(so + moff + r * (PAD * 2) + kg * 16,
                 &S[(size_t)(base + r) * K + k0 + kg * 8]);
        }
    };
    auto load_chunk = [&](int c) {
        const int k0 = c * BK;
        const uint32_t so = sb + (c & 1) * STGB;
        load_mat(Ah, m0, OFF_AH, k0, so);
        load_mat(Bh, n0, OFF_BH, k0, so);
        if (UBL) load_mat(Bl, n0, OFF_BL, k0, so);
        if (UAL) load_mat(Al, m0, OFF_AL, k0, so);
        cp_commit();
    };

    const int nch = K / BK;
    load_chunk(0);
    load_chunk(1);

    for (int c = 0; c < nch; c++) {
        if (c + 1 < nch) cp_wait<1>(); else cp_wait<0>();
        __syncthreads();

        const uint32_t stg = sb + (c & 1) * STGB;

#pragma unroll
        for (int ks = 0; ks < 2; ks++) {
            const uint32_t kb2 = ks * 32;
            unsigned ah[2][4], al[2][4];
            ldsm4(ah[0], stg + OFF_AH + offA + kb2);
            ldsm4(ah[1], stg + OFF_AH + offA + 16 * (PAD * 2) + kb2);
            if (UAL) {
                ldsm4(al[0], stg + OFF_AL + offA + kb2);
                ldsm4(al[1], stg + OFF_AL + offA + 16 * (PAD * 2) + kb2);
            }
#pragma unroll
            for (int np = 0; np < 4; np++) {
                unsigned bh[4], bl[4];
                ldsm4(bh, stg + OFF_BH + offB + np * 16 * (PAD * 2) + kb2);
                if (UBL) ldsm4(bl, stg + OFF_BL + offB + np * 16 * (PAD * 2) + kb2);
                mma16816(acc[0][2 * np],     ah[0], bh[0], bh[1]);
                mma16816(acc[0][2 * np + 1], ah[0], bh[2], bh[3]);
                mma16816(acc[1][2 * np],     ah[1], bh[0], bh[1]);
                mma16816(acc[1][2 * np + 1], ah[1], bh[2], bh[3]);
                if (UBL) {
                    mma16816(acc[0][2 * np],     ah[0], bl[0], bl[1]);
                    mma16816(acc[0][2 * np + 1], ah[0], bl[2], bl[3]);
                    mma16816(acc[1][2 * np],     ah[1], bl[0], bl[1]);
                    mma16816(acc[1][2 * np + 1], ah[1], bl[2], bl[3]);
                }
                if (UAL) {
                    mma16816(acc[0][2 * np],     al[0], bh[0], bh[1]);
                    mma16816(acc[0][2 * np + 1], al[0], bh[2], bh[3]);
                    mma16816(acc[1][2 * np],     al[1], bh[0], bh[1]);
                    mma16816(acc[1][2 * np + 1], al[1], bh[2], bh[3]);
                }
            }
        }
        __syncthreads();
        if (c + 2 < nch) load_chunk(c + 2);
    }

    // ---- epilogue ----
    float* Yf  = (EPI == 3) ? (Yfg + strY * bz) : nullptr;
    __half* Yh = (EPI < 3) ? (Yhg + strY * bz) : nullptr;
    __half* Yl = (EPI == 0) ? (Ylg + strY * bz) : nullptr;
    const float sc = (EPI == 3) ? *aux : 0.f;

#pragma unroll
    for (int mt = 0; mt < 2; mt++)
#pragma unroll
        for (int r2 = 0; r2 < 2; r2++) {
            const int m = m0 + wm + mt * 16 + grp + 8 * r2;
            const float bvr = (EPI == 2) ? aux[m] : 0.f;
#pragma unroll
            for (int nt = 0; nt < 8; nt++) {
                const int n = n0 + wn + nt * 8 + qid * 2;
                float v0 = acc[mt][nt][r2 * 2 + 0];
                float v1 = acc[mt][nt][r2 * 2 + 1];
                if (EPI <= 1) { v0 += aux[n]; v1 += aux[n + 1]; }
                if (EPI == 2) { v0 += bvr;    v1 += bvr; }
                if (EPI == 3) { v0 *= sc;     v1 *= sc; }
                const size_t off = (size_t)m * ldY + n;
                if (EPI == 3) {
                    *(float2*)&Yf[off] = make_float2(v0, v1);
                } else if (EPI == 0) {
                    __half h0, l0, h1, l1;
                    split2(v0, h0, l0); split2(v1, h1, l1);
                    *(__half2*)&Yh[off] = __halves2half2(h0, h1);
                    *(__half2*)&Yl[off] = __halves2half2(l0, l1);
                } else {
                    *(__half2*)&Yh[off] =
                        __halves2half2(__float2half_rn(v0), __float2half_rn(v1));
                }
            }
        }
}

// ============================================================================
// Pure-f16 NT HGEMM (single pass, BK=64): out = A @ B^T + res  (unchanged R8)
// ============================================================================
__global__ __launch_bounds__(256, 2)
void hgemm_f16(const __half* __restrict__ Ag, const __half* __restrict__ Bg,
               const float* __restrict__ resg, float* __restrict__ Yg,
               int K, int ldY, size_t strA, size_t strB, size_t strY)
{
    extern __shared__ char smem[];
    const uint32_t sb = smem_u32(smem);

    const int bz = blockIdx.z;
    const __half* A = Ag + strA * bz;
    const __half* B = Bg + strB * bz;
    const float* res = resg + strY * bz;
    float* Y = Yg + strY * bz;

    const int n0 = blockIdx.x * 128;
    const int m0 = blockIdx.y * 128;
    const int t    = threadIdx.x;
    const int lane = t & 31;
    const int warp = t >> 5;
    const int wm   = (warp & 3) * 32;
    const int wn   = (warp >> 2) * 64;
    const int grp  = lane >> 2;
    const int qid  = lane & 3;

    const uint32_t offA = (uint32_t)(wm + (lane & 15)) * (PAD2 * 2) + (lane >> 4) * 16;
    const uint32_t offB = (uint32_t)(wn + ((lane >> 4) & 1) * 8 + (lane & 7)) * (PAD2 * 2)
                        + ((lane >> 3) & 1) * 16;

    float acc[2][8][4];
#pragma unroll
    for (int mt = 0; mt < 2; mt++)
#pragma unroll
        for (int nt = 0; nt < 8; nt++)
#pragma unroll
            for (int r = 0; r < 4; r++) acc[mt][nt][r] = 0.f;

    auto load_chunk = [&](int c) {
        const int k0 = c * BK2;
        const uint32_t so = sb + (c & 1) * STG2_B;
#pragma unroll
        for (int i = 0; i < 4; i++) {
            const int idx = t + 256 * i;
            const int kg = idx & 7, r = idx >> 3;
            cp16(so + r * (PAD2 * 2) + kg * 16,
                 &A[(size_t)(m0 + r) * K + k0 + kg * 8]);
        }
#pragma unroll
        for (int i = 0; i < 4; i++) {
            const int idx = t + 256 * i;
            const int kg = idx & 7, r = idx >> 3;
            cp16(so + MAT2_B + r * (PAD2 * 2) + kg * 16,
                 &B[(size_t)(n0 + r) * K + k0 + kg * 8]);
        }
        cp_commit();
    };

    const int nch = K / BK2;
    load_chunk(0);
    load_chunk(1);

    for (int c = 0; c < nch; c++) {
        if (c + 1 < nch) cp_wait<1>(); else cp_wait<0>();
        __syncthreads();

        const uint32_t stg = sb + (c & 1) * STG2_B;

#pragma unroll
        for (int ks = 0; ks < 4; ks++) {
            const uint32_t kb2 = ks * 32;
            unsigned a[2][4];
            ldsm4(a[0], stg + offA + kb2);
            ldsm4(a[1], stg + offA + 16 * (PAD2 * 2) + kb2);
#pragma unroll
            for (int np = 0; np < 4; np++) {
                unsigned b[4];
                ldsm4(b, stg + MAT2_B + offB + np * 16 * (PAD2 * 2) + kb2);
                mma16816(acc[0][2 * np],     a[0], b[0], b[1]);
                mma16816(acc[0][2 * np + 1], a[0], b[2], b[3]);
                mma16816(acc[1][2 * np],     a[1], b[0], b[1]);
                mma16816(acc[1][2 * np + 1], a[1], b[2], b[3]);
            }
        }
        __syncthreads();
        if (c + 2 < nch) load_chunk(c + 2);
    }

#pragma unroll
    for (int mt = 0; mt < 2; mt++)
#pragma unroll
        for (int r2 = 0; r2 < 2; r2++) {
            const int m = m0 + wm + mt * 16 + grp + 8 * r2;
#pragma unroll
            for (int nt = 0; nt < 8; nt++) {
                const int n = n0 + wn + nt * 8 + qid * 2;
                const size_t off = (size_t)m * ldY + n;
                float v0 = acc[mt][nt][r2 * 2 + 0] + res[off];
                float v1 = acc[mt][nt][r2 * 2 + 1] + res[off + 1];
                *(float2*)&Y[off] = make_float2(v0, v1);
            }
        }
}

// ---------------- softmax over rows of S, emit f16 P -------------------------
__global__ void softmax_f16(const float* __restrict__ S, __half* __restrict__ Ph)
{
    __shared__ float red[256];
    const size_t ro = (size_t)blockIdx.x * NSP;
    const float* r = S + ro;
    const int t = threadIdx.x;

    float v[9];
    float mx = -1e30f;
#pragma unroll
    for (int i = 0; i < 9; i++) { v[i] = r[t + i * 256]; mx = fmaxf(mx, v[i]); }
    red[t] = mx;
    __syncthreads();
    for (int s = 128; s > 0; s >>= 1) {
        if (t < s) red[t] = fmaxf(red[t], red[t + s]);
        __syncthreads();
    }
    mx = red[0];
    __syncthreads();
    float sum = 0.f;
#pragma unroll
    for (int i = 0; i < 9; i++) { v[i] = __expf(v[i] - mx); sum += v[i]; }
    red[t] = sum;
    __syncthreads();
    for (int s = 128; s > 0; s >>= 1) {
        if (t < s) red[t] += red[t + s];
        __syncthreads();
    }
    const float inv = 1.0f / red[0];
#pragma unroll
    for (int i = 0; i < 9; i++)
        Ph[ro + t + i * 256] = __float2half_rn(v[i] * inv);
}

// ============================================================================
// Launch
// ============================================================================
extern "C" void kernel_launch(void* const* d_in, const int* in_sizes, int n_in,
                              void* d_out, int out_size)
{
    const float* img   = (const float*)d_in[0];
    const float* text  = (const float*)d_in[1];
    const float* w_tp  = (const float*)d_in[2];
    const float* b_tp  = (const float*)d_in[3];
    const float* w_q   = (const float*)d_in[4];
    const float* b_q   = (const float*)d_in[5];
    const float* w_k   = (const float*)d_in[6];
    const float* b_k   = (const float*)d_in[7];
    const float* w_v   = (const float*)d_in[8];
    const float* b_v   = (const float*)d_in[9];
    const float* scale = (const float*)d_in[10];

    __half *tTh, *tTl, *iTh, *iTl, *wh, *wl, *tfh, *tfl, *qh, *kh, *kl, *vh, *ph;
    float* sp;
    cudaGetSymbolAddress((void**)&tTh, g_tT_hi);  cudaGetSymbolAddress((void**)&tTl, g_tT_lo);
    cudaGetSymbolAddress((void**)&iTh, g_iT_hi);  cudaGetSymbolAddress((void**)&iTl, g_iT_lo);
    cudaGetSymbolAddress((void**)&wh,  g_w_hi);   cudaGetSymbolAddress((void**)&wl,  g_w_lo);
    cudaGetSymbolAddress((void**)&tfh, g_tfT_hi); cudaGetSymbolAddress((void**)&tfl, g_tfT_lo);
    cudaGetSymbolAddress((void**)&qh,  g_qT_hi);
    cudaGetSymbolAddress((void**)&kh,  g_kT_hi);  cudaGetSymbolAddress((void**)&kl,  g_kT_lo);
    cudaGetSymbolAddress((void**)&vh,  g_v_hi);
    cudaGetSymbolAddress((void**)&ph,  g_P_hi);
    cudaGetSymbolAddress((void**)&sp,  g_S);

    cudaFuncSetAttribute((const void*)hgemm_nt<true,true,0>,
                         cudaFuncAttributeMaxDynamicSharedMemorySize, 2 * 4 * MAT_B);
    cudaFuncSetAttribute((const void*)hgemm_nt<true,true,1>,
                         cudaFuncAttributeMaxDynamicSharedMemorySize, 2 * 4 * MAT_B);
    cudaFuncSetAttribute((const void*)hgemm_nt<false,false,2>,
                         cudaFuncAttributeMaxDynamicSharedMemorySize, 2 * 2 * MAT_B);
    cudaFuncSetAttribute((const void*)hgemm_nt<false,true,3>,
                         cudaFuncAttributeMaxDynamicSharedMemorySize, 2 * 3 * MAT_B);
    cudaFuncSetAttribute((const void*)hgemm_f16,
                         cudaFuncAttributeMaxDynamicSharedMemorySize, SMEM2_TOTAL);

    const size_t sNC = (size_t)NSP * CH;
    const size_t sNN = (size_t)NSP * NSP;
    const size_t sW  = (size_t)CH * CH;

    dim3 tb(32, 8);
    dim3 tg(NSP / 32, CH / 32, BATCH);
    split_transpose<<<tg, tb>>>(text, tTh, tTl);
    split_transpose<<<tg, tb>>>(img,  iTh, iTl);
    split_w<<<dim3(CH * CH / 256, 1, 4), 256>>>(w_tp, w_q, w_k, w_v, wh, wl);

    dim3 blk(256);
    dim3 grid_p (CH / 128, NSP / 128, BATCH);   // M=NSP, N=CH
    dim3 grid_v (NSP / 128, CH / 128, BATCH);   // M=CH,  N=NSP
    dim3 grid_s (NSP / 128, NSP / 128, BATCH);  // M=NSP, N=NSP

    // tf (3-pass, split out: feeds K 3-pass and V hi)
    hgemm_nt<true,true,0><<<grid_p, blk, 2 * 4 * MAT_B>>>(
        tTh, tTl, wh, wl, b_tp, nullptr, tfh, tfl, CH, CH, sNC, 0, sNC);
    // Q (3-pass, hi out only — S drops ql·kh)
    hgemm_nt<true,true,1><<<grid_p, blk, 2 * 4 * MAT_B>>>(
        iTh, iTl, wh + sW, wl + sW, b_q, nullptr, qh, nullptr, CH, CH, sNC, 0, sNC);
    // K (3-pass, split out — S keeps qh·kl)
    hgemm_nt<true,true,0><<<grid_p, blk, 2 * 4 * MAT_B>>>(
        tfh, tfl, wh + 2 * sW, wl + 2 * sW, b_k, nullptr, kh, kl, CH, CH, sNC, 0, sNC);
    // V (1-pass hi, bias[m], hi out)
    hgemm_nt<false,false,2><<<grid_v, blk, 2 * 2 * MAT_B>>>(
        wh + 3 * sW, nullptr, tfh, nullptr, b_v, nullptr, vh, nullptr, CH, NSP, 0, sNC, sNC);
    // S = scale * (Qh·Kh + Qh·Kl)  (2-pass, f32 out)
    hgemm_nt<false,true,3><<<grid_s, blk, 2 * 3 * MAT_B>>>(
        qh, nullptr, kh, kl, scale, sp, nullptr, nullptr, CH, NSP, sNC, sNC, sNN);
    // P = softmax(S), f16
    softmax_f16<<<BATCH * NSP, 256>>>(sp, ph);
    // out = V_hi @ P^T + img
    hgemm_f16<<<grid_v, blk, SMEM2_TOTAL>>>(vh, ph, img, (float*)d_out,
                                            NSP, NSP, sNC, sNN, sNC);
}

// round 10
// speedup vs baseline: 2.0922x; 1.3444x over previous
#include <cuda_runtime.h>
#include <cuda_fp16.h>
#include <cstdint>

#define NSP   2304
#define CH    512
#define BATCH 8
#define BK    32
#define PAD   40                       // halves per smem row (16B-aligned, conflict-free)
#define MAT_B (128 * PAD * 2)          // 10240 bytes per matrix tile

// ---- pure-f16 GEMM kernel params (BK=64) ----
#define BK2    64
#define PAD2   72
#define MAT2_B (128 * PAD2 * 2)        // 18432 bytes
#define STG2_B (2 * MAT2_B)
#define SMEM2_TOTAL (2 * STG2_B)       // 73728 bytes

// ---------------- scratch (device globals; no allocations) ------------------
__device__ __half g_tT_hi [(size_t)BATCH * NSP * CH];
__device__ __half g_iT_hi [(size_t)BATCH * NSP * CH];
__device__ __half g_w_hi  [(size_t)4 * CH * CH];
__device__ __half g_w_lo  [(size_t)4 * CH * CH];
__device__ __half g_tfT_hi[(size_t)BATCH * NSP * CH];
__device__ __half g_qT_hi [(size_t)BATCH * NSP * CH];
__device__ __half g_kT_hi [(size_t)BATCH * NSP * CH];
__device__ __half g_v_hi  [(size_t)BATCH * CH * NSP];
__device__ float  g_S     [(size_t)BATCH * NSP * NSP];
__device__ __half g_P_hi  [(size_t)BATCH * NSP * NSP];

// ---------------- helpers ----------------------------------------------------
__device__ __forceinline__ uint32_t smem_u32(const void* p) {
    uint32_t a;
    asm("{ .reg .u64 t; cvta.to.shared.u64 t, %1; cvt.u32.u64 %0, t; }" : "=r"(a) : "l"(p));
    return a;
}
__device__ __forceinline__ void cp16(uint32_t saddr, const void* g) {
    asm volatile("cp.async.cg.shared.global [%0], [%1], 16;\n" :: "r"(saddr), "l"(g));
}
__device__ __forceinline__ void cp_commit() { asm volatile("cp.async.commit_group;\n"); }
template<int N> __device__ __forceinline__ void cp_wait() {
    asm volatile("cp.async.wait_group %0;\n" :: "n"(N));
}
__device__ __forceinline__ void ldsm4(unsigned (&r)[4], uint32_t addr) {
    asm volatile("ldmatrix.sync.aligned.m8n8.x4.shared.b16 {%0,%1,%2,%3}, [%4];"
        : "=r"(r[0]), "=r"(r[1]), "=r"(r[2]), "=r"(r[3]) : "r"(addr));
}
__device__ __forceinline__ void mma16816(float (&d)[4], const unsigned (&a)[4],
                                         unsigned b0, unsigned b1) {
    asm volatile(
        "mma.sync.aligned.m16n8k16.row.col.f32.f16.f16.f32 "
        "{%0,%1,%2,%3}, {%4,%5,%6,%7}, {%8,%9}, {%0,%1,%2,%3};\n"
        : "+f"(d[0]), "+f"(d[1]), "+f"(d[2]), "+f"(d[3])
        : "r"(a[0]), "r"(a[1]), "r"(a[2]), "r"(a[3]), "r"(b0), "r"(b1));
}
__device__ __forceinline__ void split2(float f, __half& h, __half& l) {
    h = __float2half_rn(f);
    l = __float2half_rn(f - __half2float(h));
}

// ---------------- pre-pass: transpose fp32 [C][N] -> f16 [N][C] (hi only) ----
__global__ void transpose_f16(const float* __restrict__ in, __half* __restrict__ ohi)
{
    __shared__ float tile[32][33];
    const int bz = blockIdx.z;
    const float* I = in  + (size_t)bz * CH * NSP;
    __half* H = ohi + (size_t)bz * NSP * CH;
    const int n0 = blockIdx.x * 32, c0 = blockIdx.y * 32;
    const int tx = threadIdx.x, ty = threadIdx.y;
#pragma unroll
    for (int j = 0; j < 32; j += 8)
        tile[ty + j][tx] = I[(size_t)(c0 + ty + j) * NSP + n0 + tx];
    __syncthreads();
#pragma unroll
    for (int j = 0; j < 32; j += 8)
        H[(size_t)(n0 + ty + j) * CH + c0 + tx] = __float2half_rn(tile[tx][ty + j]);
}

__global__ void split_w(const float* __restrict__ w0, const float* __restrict__ w1,
                        const float* __restrict__ w2, const float* __restrict__ w3,
                        __half* __restrict__ hi, __half* __restrict__ lo)
{
    const int z = blockIdx.z;
    const float* w = (z == 0) ? w0 : (z == 1) ? w1 : (z == 2) ? w2 : w3;
    const int i = blockIdx.x * 256 + threadIdx.x;
    __half h, l; split2(w[i], h, l);
    hi[(size_t)z * CH * CH + i] = h;
    lo[(size_t)z * CH * CH + i] = l;
}

// ============================================================================
// Projection GEMM: Y[m][n] = sum_k A[m][k]*B[n][k], A hi-only; B hi (+lo if UBL).
// BIASN: bias indexed by n (tf/Q/K) else by m (V). Output: f16 hi.
// ============================================================================
template<bool UBL, bool BIASN>
__global__ __launch_bounds__(256, 2)
void hgemm_proj(const __half* __restrict__ Agh,
                const __half* __restrict__ Bgh, const __half* __restrict__ Bgl,
                const float* __restrict__ bias, __half* __restrict__ Yhg,
                int K, int ldY, size_t strA, size_t strB, size_t strY)
{
    constexpr int NMAT = UBL ? 3 : 2;
    constexpr int STGB = NMAT * MAT_B;
    constexpr uint32_t OFF_AH = 0;
    constexpr uint32_t OFF_BH = MAT_B;
    constexpr uint32_t OFF_BL = 2 * MAT_B;

    extern __shared__ char smem[];
    const uint32_t sb = smem_u32(smem);

    const int bz = blockIdx.z;
    const __half* Ah = Agh + strA * bz;
    const __half* Bh = Bgh + strB * bz;
    const __half* Bl = UBL ? (Bgl + strB * bz) : nullptr;

    const int n0 = blockIdx.x * 128;
    const int m0 = blockIdx.y * 128;
    const int t    = threadIdx.x;
    const int lane = t & 31;
    const int warp = t >> 5;
    const int wm   = (warp & 3) * 32;
    const int wn   = (warp >> 2) * 64;
    const int grp  = lane >> 2;
    const int qid  = lane & 3;

    const uint32_t offA = (uint32_t)(wm + (lane & 15)) * (PAD * 2) + (lane >> 4) * 16;
    const uint32_t offB = (uint32_t)(wn + ((lane >> 4) & 1) * 8 + (lane & 7)) * (PAD * 2)
                        + ((lane >> 3) & 1) * 16;

    float acc[2][8][4];
#pragma unroll
    for (int mt = 0; mt < 2; mt++)
#pragma unroll
        for (int nt = 0; nt < 8; nt++)
#pragma unroll
            for (int r = 0; r < 4; r++) acc[mt][nt][r] = 0.f;

    auto load_mat = [&](const __half* S, int base, uint32_t moff, int k0, uint32_t so) {
#pragma unroll
        for (int i = 0; i < 2; i++) {
            const int idx = t + 256 * i;
            const int kg = idx & 3, r = idx >> 2;
            cp16(so + moff + r * (PAD * 2) + kg * 16,
                 &S[(size_t)(base + r) * K + k0 + kg * 8]);
        }
    };
    auto load_chunk = [&](int c) {
        const int k0 = c * BK;
        const uint32_t so = sb + (c & 1) * STGB;
        load_mat(Ah, m0, OFF_AH, k0, so);
        load_mat(Bh, n0, OFF_BH, k0, so);
        if (UBL) load_mat(Bl, n0, OFF_BL, k0, so);
        cp_commit();
    };

    const int nch = K / BK;
    load_chunk(0);
    load_chunk(1);

    for (int c = 0; c < nch; c++) {
        if (c + 1 < nch) cp_wait<1>(); else cp_wait<0>();
        __syncthreads();

        const uint32_t stg = sb + (c & 1) * STGB;

#pragma unroll
        for (int ks = 0; ks < 2; ks++) {
            const uint32_t kb2 = ks * 32;
            unsigned ah[2][4];
            ldsm4(ah[0], stg + OFF_AH + offA + kb2);
            ldsm4(ah[1], stg + OFF_AH + offA + 16 * (PAD * 2) + kb2);
#pragma unroll
            for (int np = 0; np < 4; np++) {
                unsigned bh[4], bl[4];
                ldsm4(bh, stg + OFF_BH + offB + np * 16 * (PAD * 2) + kb2);
                if (UBL) ldsm4(bl, stg + OFF_BL + offB + np * 16 * (PAD * 2) + kb2);
                mma16816(acc[0][2 * np],     ah[0], bh[0], bh[1]);
                mma16816(acc[0][2 * np + 1], ah[0], bh[2], bh[3]);
                mma16816(acc[1][2 * np],     ah[1], bh[0], bh[1]);
                mma16816(acc[1][2 * np + 1], ah[1], bh[2], bh[3]);
                if (UBL) {
                    mma16816(acc[0][2 * np],     ah[0], bl[0], bl[1]);
                    mma16816(acc[0][2 * np + 1], ah[0], bl[2], bl[3]);
                    mma16816(acc[1][2 * np],     ah[1], bl[0], bl[1]);
                    mma16816(acc[1][2 * np + 1], ah[1], bl[2], bl[3]);
                }
            }
        }
        __syncthreads();
        if (c + 2 < nch) load_chunk(c + 2);
    }

    __half* Yh = Yhg + strY * bz;
#pragma unroll
    for (int mt = 0; mt < 2; mt++)
#pragma unroll
        for (int r2 = 0; r2 < 2; r2++) {
            const int m = m0 + wm + mt * 16 + grp + 8 * r2;
            const float bvr = BIASN ? 0.f : bias[m];
#pragma unroll
            for (int nt = 0; nt < 8; nt++) {
                const int n = n0 + wn + nt * 8 + qid * 2;
                float v0 = acc[mt][nt][r2 * 2 + 0];
                float v1 = acc[mt][nt][r2 * 2 + 1];
                if (BIASN) { v0 += bias[n]; v1 += bias[n + 1]; }
                else       { v0 += bvr;     v1 += bvr; }
                const size_t off = (size_t)m * ldY + n;
                *(__half2*)&Yh[off] =
                    __halves2half2(__float2half_rn(v0), __float2half_rn(v1));
            }
        }
}

// ============================================================================
// Pure-f16 NT HGEMM (single pass, BK=64): Y = A @ B^T (+epilogue), fp32 out.
// EPI 0: *(*aux)   (S = scale * Q K^T)
// EPI 1: +res[m][n] (out = V P^T + img)
// ============================================================================
template<int EPI>
__global__ __launch_bounds__(256, 2)
void hgemm_f16(const __half* __restrict__ Ag, const __half* __restrict__ Bg,
               const float* __restrict__ aux, const float* __restrict__ resg,
               float* __restrict__ Yg,
               int K, int ldY, size_t strA, size_t strB, size_t strY)
{
    extern __shared__ char smem[];
    const uint32_t sb = smem_u32(smem);

    const int bz = blockIdx.z;
    const __half* A = Ag + strA * bz;
    const __half* B = Bg + strB * bz;
    const float* res = (EPI == 1) ? (resg + strY * bz) : nullptr;
    float* Y = Yg + strY * bz;

    const int n0 = blockIdx.x * 128;
    const int m0 = blockIdx.y * 128;
    const int t    = threadIdx.x;
    const int lane = t & 31;
    const int warp = t >> 5;
    const int wm   = (warp & 3) * 32;
    const int wn   = (warp >> 2) * 64;
    const int grp  = lane >> 2;
    const int qid  = lane & 3;

    const uint32_t offA = (uint32_t)(wm + (lane & 15)) * (PAD2 * 2) + (lane >> 4) * 16;
    const uint32_t offB = (uint32_t)(wn + ((lane >> 4) & 1) * 8 + (lane & 7)) * (PAD2 * 2)
                        + ((lane >> 3) & 1) * 16;

    float acc[2][8][4];
#pragma unroll
    for (int mt = 0; mt < 2; mt++)
#pragma unroll
        for (int nt = 0; nt < 8; nt++)
#pragma unroll
            for (int r = 0; r < 4; r++) acc[mt][nt][r] = 0.f;

    auto load_chunk = [&](int c) {
        const int k0 = c * BK2;
        const uint32_t so = sb + (c & 1) * STG2_B;
#pragma unroll
        for (int i = 0; i < 4; i++) {
            const int idx = t + 256 * i;
            const int kg = idx & 7, r = idx >> 3;
            cp16(so + r * (PAD2 * 2) + kg * 16,
                 &A[(size_t)(m0 + r) * K + k0 + kg * 8]);
        }
#pragma unroll
        for (int i = 0; i < 4; i++) {
            const int idx = t + 256 * i;
            const int kg = idx & 7, r = idx >> 3;
            cp16(so + MAT2_B + r * (PAD2 * 2) + kg * 16,
                 &B[(size_t)(n0 + r) * K + k0 + kg * 8]);
        }
        cp_commit();
    };

    const int nch = K / BK2;
    load_chunk(0);
    load_chunk(1);

    for (int c = 0; c < nch; c++) {
        if (c + 1 < nch) cp_wait<1>(); else cp_wait<0>();
        __syncthreads();

        const uint32_t stg = sb + (c & 1) * STG2_B;

#pragma unroll
        for (int ks = 0; ks < 4; ks++) {
            const uint32_t kb2 = ks * 32;
            unsigned a[2][4];
            ldsm4(a[0], stg + offA + kb2);
            ldsm4(a[1], stg + offA + 16 * (PAD2 * 2) + kb2);
#pragma unroll
            for (int np = 0; np < 4; np++) {
                unsigned b[4];
                ldsm4(b, stg + MAT2_B + offB + np * 16 * (PAD2 * 2) + kb2);
                mma16816(acc[0][2 * np],     a[0], b[0], b[1]);
                mma16816(acc[0][2 * np + 1], a[0], b[2], b[3]);
                mma16816(acc[1][2 * np],     a[1], b[0], b[1]);
                mma16816(acc[1][2 * np + 1], a[1], b[2], b[3]);
            }
        }
        __syncthreads();
        if (c + 2 < nch) load_chunk(c + 2);
    }

    const float sc = (EPI == 0) ? *aux : 0.f;
#pragma unroll
    for (int mt = 0; mt < 2; mt++)
#pragma unroll
        for (int r2 = 0; r2 < 2; r2++) {
            const int m = m0 + wm + mt * 16 + grp + 8 * r2;
#pragma unroll
            for (int nt = 0; nt < 8; nt++) {
                const int n = n0 + wn + nt * 8 + qid * 2;
                const size_t off = (size_t)m * ldY + n;
                float v0 = acc[mt][nt][r2 * 2 + 0];
                float v1 = acc[mt][nt][r2 * 2 + 1];
                if (EPI == 0) { v0 *= sc; v1 *= sc; }
                else          { v0 += res[off]; v1 += res[off + 1]; }
                *(float2*)&Y[off] = make_float2(v0, v1);
            }
        }
}

// ---------------- softmax over rows of S, emit f16 P -------------------------
__global__ void softmax_f16(const float* __restrict__ S, __half* __restrict__ Ph)
{
    __shared__ float red[256];
    const size_t ro = (size_t)blockIdx.x * NSP;
    const float* r = S + ro;
    const int t = threadIdx.x;

    float v[9];
    float mx = -1e30f;
#pragma unroll
    for (int i = 0; i < 9; i++) { v[i] = r[t + i * 256]; mx = fmaxf(mx, v[i]); }
    red[t] = mx;
    __syncthreads();
    for (int s = 128; s > 0; s >>= 1) {
        if (t < s) red[t] = fmaxf(red[t], red[t + s]);
        __syncthreads();
    }
    mx = red[0];
    __syncthreads();
    float sum = 0.f;
#pragma unroll
    for (int i = 0; i < 9; i++) { v[i] = __expf(v[i] - mx); sum += v[i]; }
    red[t] = sum;
    __syncthreads();
    for (int s = 128; s > 0; s >>= 1) {
        if (t < s) red[t] += red[t + s];
        __syncthreads();
    }
    const float inv = 1.0f / red[0];
#pragma unroll
    for (int i = 0; i < 9; i++)
        Ph[ro + t + i * 256] = __float2half_rn(v[i] * inv);
}

// ============================================================================
// Launch
// ============================================================================
extern "C" void kernel_launch(void* const* d_in, const int* in_sizes, int n_in,
                              void* d_out, int out_size)
{
    const float* img   = (const float*)d_in[0];
    const float* text  = (const float*)d_in[1];
    const float* w_tp  = (const float*)d_in[2];
    const float* b_tp  = (const float*)d_in[3];
    const float* w_q   = (const float*)d_in[4];
    const float* b_q   = (const float*)d_in[5];
    const float* w_k   = (const float*)d_in[6];
    const float* b_k   = (const float*)d_in[7];
    const float* w_v   = (const float*)d_in[8];
    const float* b_v   = (const float*)d_in[9];
    const float* scale = (const float*)d_in[10];

    __half *tTh, *iTh, *wh, *wl, *tfh, *qh, *kh, *vh, *ph;
    float* sp;
    cudaGetSymbolAddress((void**)&tTh, g_tT_hi);
    cudaGetSymbolAddress((void**)&iTh, g_iT_hi);
    cudaGetSymbolAddress((void**)&wh,  g_w_hi);
    cudaGetSymbolAddress((void**)&wl,  g_w_lo);
    cudaGetSymbolAddress((void**)&tfh, g_tfT_hi);
    cudaGetSymbolAddress((void**)&qh,  g_qT_hi);
    cudaGetSymbolAddress((void**)&kh,  g_kT_hi);
    cudaGetSymbolAddress((void**)&vh,  g_v_hi);
    cudaGetSymbolAddress((void**)&ph,  g_P_hi);
    cudaGetSymbolAddress((void**)&sp,  g_S);

    cudaFuncSetAttribute((const void*)hgemm_proj<true,true>,
                         cudaFuncAttributeMaxDynamicSharedMemorySize, 2 * 3 * MAT_B);
    cudaFuncSetAttribute((const void*)hgemm_proj<false,false>,
                         cudaFuncAttributeMaxDynamicSharedMemorySize, 2 * 2 * MAT_B);
    cudaFuncSetAttribute((const void*)hgemm_f16<0>,
                         cudaFuncAttributeMaxDynamicSharedMemorySize, SMEM2_TOTAL);
    cudaFuncSetAttribute((const void*)hgemm_f16<1>,
                         cudaFuncAttributeMaxDynamicSharedMemorySize, SMEM2_TOTAL);

    const size_t sNC = (size_t)NSP * CH;
    const size_t sNN = (size_t)NSP * NSP;
    const size_t sW  = (size_t)CH * CH;

    dim3 tb(32, 8);
    dim3 tg(NSP / 32, CH / 32, BATCH);
    transpose_f16<<<tg, tb>>>(text, tTh);
    transpose_f16<<<tg, tb>>>(img,  iTh);
    split_w<<<dim3(CH * CH / 256, 1, 4), 256>>>(w_tp, w_q, w_k, w_v, wh, wl);

    dim3 blk(256);
    dim3 grid_p (CH / 128, NSP / 128, BATCH);   // M=NSP, N=CH
    dim3 grid_v (NSP / 128, CH / 128, BATCH);   // M=CH,  N=NSP
    dim3 grid_s (NSP / 128, NSP / 128, BATCH);  // M=NSP, N=NSP

    // tf (2-pass: text_h·w_h + text_h·w_l, bias[n] -> hi f16)
    hgemm_proj<true,true><<<grid_p, blk, 2 * 3 * MAT_B>>>(
        tTh, wh, wl, b_tp, tfh, CH, CH, sNC, 0, sNC);
    // Q (2-pass)
    hgemm_proj<true,true><<<grid_p, blk, 2 * 3 * MAT_B>>>(
        iTh, wh + sW, wl + sW, b_q, qh, CH, CH, sNC, 0, sNC);
    // K (2-pass)
    hgemm_proj<true,true><<<grid_p, blk, 2 * 3 * MAT_B>>>(
        tfh, wh + 2 * sW, wl + 2 * sW, b_k, kh, CH, CH, sNC, 0, sNC);
    // V (1-pass, bias[m])
    hgemm_proj<false,false><<<grid_v, blk, 2 * 2 * MAT_B>>>(
        wh + 3 * sW, tfh, nullptr, b_v, vh, CH, NSP, 0, sNC, sNC);
    // S = scale * Qh Kh^T  (pure f16, BK=64)
    hgemm_f16<0><<<grid_s, blk, SMEM2_TOTAL>>>(
        qh, kh, scale, nullptr, sp, CH, NSP, sNC, sNC, sNN);
    // P = softmax(S), f16
    softmax_f16<<<BATCH * NSP, 256>>>(sp, ph);
    // out = V_h P^T + img
    hgemm_f16<1><<<grid_v, blk, SMEM2_TOTAL>>>(
        vh, ph, nullptr, img, (float*)d_out, NSP, NSP, sNC, sNN, sNC);
}

// round 11
// speedup vs baseline: 2.4691x; 1.1801x over previous
#include <cuda_runtime.h>
#include <cuda_fp16.h>
#include <cstdint>

#define NSP   2304
#define CH    512
#define BATCH 8

// ---- unified pure-f16 GEMM params (BK=64) ----
#define BK2    64
#define PAD2   72                      // 64+8 halves; 144B stride, conflict-free
#define MAT2_B (128 * PAD2 * 2)        // 18432 bytes
#define STG2_B (2 * MAT2_B)
#define SMEM2_TOTAL (2 * STG2_B)       // 73728 bytes

// ---------------- scratch (device globals; no allocations) ------------------
__device__ __half g_tT  [(size_t)BATCH * NSP * CH];   // text^T [n][c] f16
__device__ __half g_iT  [(size_t)BATCH * NSP * CH];   // img^T  [n][c] f16
__device__ __half g_w   [(size_t)4 * CH * CH];        // w_tp,w_q,w_k,w_v f16
__device__ __half g_tfT [(size_t)BATCH * NSP * CH];   // tf^T [n][c]
__device__ __half g_qT  [(size_t)BATCH * NSP * CH];
__device__ __half g_kT  [(size_t)BATCH * NSP * CH];
__device__ __half g_v   [(size_t)BATCH * CH * NSP];   // V [c][n]
__device__ float  g_S   [(size_t)BATCH * NSP * NSP];
__device__ __half g_P   [(size_t)BATCH * NSP * NSP];

// ---------------- helpers ----------------------------------------------------
__device__ __forceinline__ uint32_t smem_u32(const void* p) {
    uint32_t a;
    asm("{ .reg .u64 t; cvta.to.shared.u64 t, %1; cvt.u32.u64 %0, t; }" : "=r"(a) : "l"(p));
    return a;
}
__device__ __forceinline__ void cp16(uint32_t saddr, const void* g) {
    asm volatile("cp.async.cg.shared.global [%0], [%1], 16;\n" :: "r"(saddr), "l"(g));
}
__device__ __forceinline__ void cp_commit() { asm volatile("cp.async.commit_group;\n"); }
template<int N> __device__ __forceinline__ void cp_wait() {
    asm volatile("cp.async.wait_group %0;\n" :: "n"(N));
}
__device__ __forceinline__ void ldsm4(unsigned (&r)[4], uint32_t addr) {
    asm volatile("ldmatrix.sync.aligned.m8n8.x4.shared.b16 {%0,%1,%2,%3}, [%4];"
        : "=r"(r[0]), "=r"(r[1]), "=r"(r[2]), "=r"(r[3]) : "r"(addr));
}
__device__ __forceinline__ void mma16816(float (&d)[4], const unsigned (&a)[4],
                                         unsigned b0, unsigned b1) {
    asm volatile(
        "mma.sync.aligned.m16n8k16.row.col.f32.f16.f16.f32 "
        "{%0,%1,%2,%3}, {%4,%5,%6,%7}, {%8,%9}, {%0,%1,%2,%3};\n"
        : "+f"(d[0]), "+f"(d[1]), "+f"(d[2]), "+f"(d[3])
        : "r"(a[0]), "r"(a[1]), "r"(a[2]), "r"(a[3]), "r"(b0), "r"(b1));
}

// ---------------- pre-pass: transpose fp32 [C][N] -> f16 [N][C] --------------
__global__ void transpose_f16(const float* __restrict__ in, __half* __restrict__ o)
{
    __shared__ float tile[32][33];
    const int bz = blockIdx.z;
    const float* I = in + (size_t)bz * CH * NSP;
    __half* H = o + (size_t)bz * NSP * CH;
    const int n0 = blockIdx.x * 32, c0 = blockIdx.y * 32;
    const int tx = threadIdx.x, ty = threadIdx.y;
#pragma unroll
    for (int j = 0; j < 32; j += 8)
        tile[ty + j][tx] = I[(size_t)(c0 + ty + j) * NSP + n0 + tx];
    __syncthreads();
#pragma unroll
    for (int j = 0; j < 32; j += 8)
        H[(size_t)(n0 + ty + j) * CH + c0 + tx] = __float2half_rn(tile[tx][ty + j]);
}

// ---------------- pre-pass: convert the four weight matrices to f16 ----------
__global__ void convert_w(const float* __restrict__ w0, const float* __restrict__ w1,
                          const float* __restrict__ w2, const float* __restrict__ w3,
                          __half* __restrict__ o)
{
    const int z = blockIdx.z;
    const float* w = (z == 0) ? w0 : (z == 1) ? w1 : (z == 2) ? w2 : w3;
    const int i = blockIdx.x * 256 + threadIdx.x;
    o[(size_t)z * CH * CH + i] = __float2half_rn(w[i]);
}

// ============================================================================
// Unified pure-f16 NT HGEMM (BK=64, cp.async double-buffered, ldmatrix).
//   Y[m][n] = sum_k A[m][k] * B[n][k]
// EPI 0: +bias[n] -> f16   | 1: +bias[m] -> f16
// EPI 2: *(*aux)  -> fp32  | 3: +res[m][n] -> fp32
// ============================================================================
template<int EPI>
__global__ __launch_bounds__(256, 2)
void hgemm_f16(const __half* __restrict__ Ag, const __half* __restrict__ Bg,
               const float* __restrict__ aux, const float* __restrict__ resg,
               float* __restrict__ Yfg, __half* __restrict__ Yhg,
               int K, int ldY, size_t strA, size_t strB, size_t strY)
{
    extern __shared__ char smem[];
    const uint32_t sb = smem_u32(smem);

    const int bz = blockIdx.z;
    const __half* A = Ag + strA * bz;
    const __half* B = Bg + strB * bz;
    const float* res = (EPI == 3) ? (resg + strY * bz) : nullptr;

    const int n0 = blockIdx.x * 128;
    const int m0 = blockIdx.y * 128;
    const int t    = threadIdx.x;
    const int lane = t & 31;
    const int warp = t >> 5;
    const int wm   = (warp & 3) * 32;
    const int wn   = (warp >> 2) * 64;
    const int grp  = lane >> 2;
    const int qid  = lane & 3;

    const uint32_t offA = (uint32_t)(wm + (lane & 15)) * (PAD2 * 2) + (lane >> 4) * 16;
    const uint32_t offB = (uint32_t)(wn + ((lane >> 4) & 1) * 8 + (lane & 7)) * (PAD2 * 2)
                        + ((lane >> 3) & 1) * 16;

    float acc[2][8][4];
#pragma unroll
    for (int mt = 0; mt < 2; mt++)
#pragma unroll
        for (int nt = 0; nt < 8; nt++)
#pragma unroll
            for (int r = 0; r < 4; r++) acc[mt][nt][r] = 0.f;

    auto load_chunk = [&](int c) {
        const int k0 = c * BK2;
        const uint32_t so = sb + (c & 1) * STG2_B;
#pragma unroll
        for (int i = 0; i < 4; i++) {
            const int idx = t + 256 * i;
            const int kg = idx & 7, r = idx >> 3;
            cp16(so + r * (PAD2 * 2) + kg * 16,
                 &A[(size_t)(m0 + r) * K + k0 + kg * 8]);
        }
#pragma unroll
        for (int i = 0; i < 4; i++) {
            const int idx = t + 256 * i;
            const int kg = idx & 7, r = idx >> 3;
            cp16(so + MAT2_B + r * (PAD2 * 2) + kg * 16,
                 &B[(size_t)(n0 + r) * K + k0 + kg * 8]);
        }
        cp_commit();
    };

    const int nch = K / BK2;
    load_chunk(0);
    if (nch > 1) load_chunk(1);

    for (int c = 0; c < nch; c++) {
        if (c + 1 < nch) cp_wait<1>(); else cp_wait<0>();
        __syncthreads();

        const uint32_t stg = sb + (c & 1) * STG2_B;

#pragma unroll
        for (int ks = 0; ks < 4; ks++) {
            const uint32_t kb2 = ks * 32;
            unsigned a[2][4];
            ldsm4(a[0], stg + offA + kb2);
            ldsm4(a[1], stg + offA + 16 * (PAD2 * 2) + kb2);
#pragma unroll
            for (int np = 0; np < 4; np++) {
                unsigned b[4];
                ldsm4(b, stg + MAT2_B + offB + np * 16 * (PAD2 * 2) + kb2);
                mma16816(acc[0][2 * np],     a[0], b[0], b[1]);
                mma16816(acc[0][2 * np + 1], a[0], b[2], b[3]);
                mma16816(acc[1][2 * np],     a[1], b[0], b[1]);
                mma16816(acc[1][2 * np + 1], a[1], b[2], b[3]);
            }
        }
        __syncthreads();
        if (c + 2 < nch) load_chunk(c + 2);
    }

    // ---- epilogue ----
    float* Yf  = (EPI >= 2) ? (Yfg + strY * bz) : nullptr;
    __half* Yh = (EPI < 2) ? (Yhg + strY * bz) : nullptr;
    const float sc = (EPI == 2) ? *aux : 0.f;

#pragma unroll
    for (int mt = 0; mt < 2; mt++)
#pragma unroll
        for (int r2 = 0; r2 < 2; r2++) {
            const int m = m0 + wm + mt * 16 + grp + 8 * r2;
            const float bvr = (EPI == 1) ? aux[m] : 0.f;
#pragma unroll
            for (int nt = 0; nt < 8; nt++) {
                const int n = n0 + wn + nt * 8 + qid * 2;
                const size_t off = (size_t)m * ldY + n;
                float v0 = acc[mt][nt][r2 * 2 + 0];
                float v1 = acc[mt][nt][r2 * 2 + 1];
                if (EPI == 0) { v0 += aux[n]; v1 += aux[n + 1]; }
                if (EPI == 1) { v0 += bvr;    v1 += bvr; }
                if (EPI == 2) { v0 *= sc;     v1 *= sc; }
                if (EPI == 3) { v0 += res[off]; v1 += res[off + 1]; }
                if (EPI >= 2) {
                    *(float2*)&Yf[off] = make_float2(v0, v1);
                } else {
                    *(__half2*)&Yh[off] =
                        __halves2half2(__float2half_rn(v0), __float2half_rn(v1));
                }
            }
        }
}

// ---------------- softmax over rows of S, emit f16 P -------------------------
__global__ void softmax_f16(const float* __restrict__ S, __half* __restrict__ Ph)
{
    __shared__ float red[256];
    const size_t ro = (size_t)blockIdx.x * NSP;
    const float* r = S + ro;
    const int t = threadIdx.x;

    float v[9];
    float mx = -1e30f;
#pragma unroll
    for (int i = 0; i < 9; i++) { v[i] = r[t + i * 256]; mx = fmaxf(mx, v[i]); }
    red[t] = mx;
    __syncthreads();
    for (int s = 128; s > 0; s >>= 1) {
        if (t < s) red[t] = fmaxf(red[t], red[t + s]);
        __syncthreads();
    }
    mx = red[0];
    __syncthreads();
    float sum = 0.f;
#pragma unroll
    for (int i = 0; i < 9; i++) { v[i] = __expf(v[i] - mx); sum += v[i]; }
    red[t] = sum;
    __syncthreads();
    for (int s = 128; s > 0; s >>= 1) {
        if (t < s) red[t] += red[t + s];
        __syncthreads();
    }
    const float inv = 1.0f / red[0];
#pragma unroll
    for (int i = 0; i < 9; i++)
        Ph[ro + t + i * 256] = __float2half_rn(v[i] * inv);
}

// ============================================================================
// Launch
// ============================================================================
extern "C" void kernel_launch(void* const* d_in, const int* in_sizes, int n_in,
                              void* d_out, int out_size)
{
    const float* img   = (const float*)d_in[0];
    const float* text  = (const float*)d_in[1];
    const float* w_tp  = (const float*)d_in[2];
    const float* b_tp  = (const float*)d_in[3];
    const float* w_q   = (const float*)d_in[4];
    const float* b_q   = (const float*)d_in[5];
    const float* w_k   = (const float*)d_in[6];
    const float* b_k   = (const float*)d_in[7];
    const float* w_v   = (const float*)d_in[8];
    const float* b_v   = (const float*)d_in[9];
    const float* scale = (const float*)d_in[10];

    __half *tT, *iT, *w, *tf, *q, *k, *v, *p;
    float* sp;
    cudaGetSymbolAddress((void**)&tT, g_tT);
    cudaGetSymbolAddress((void**)&iT, g_iT);
    cudaGetSymbolAddress((void**)&w,  g_w);
    cudaGetSymbolAddress((void**)&tf, g_tfT);
    cudaGetSymbolAddress((void**)&q,  g_qT);
    cudaGetSymbolAddress((void**)&k,  g_kT);
    cudaGetSymbolAddress((void**)&v,  g_v);
    cudaGetSymbolAddress((void**)&p,  g_P);
    cudaGetSymbolAddress((void**)&sp, g_S);

    cudaFuncSetAttribute((const void*)hgemm_f16<0>,
                         cudaFuncAttributeMaxDynamicSharedMemorySize, SMEM2_TOTAL);
    cudaFuncSetAttribute((const void*)hgemm_f16<1>,
                         cudaFuncAttributeMaxDynamicSharedMemorySize, SMEM2_TOTAL);
    cudaFuncSetAttribute((const void*)hgemm_f16<2>,
                         cudaFuncAttributeMaxDynamicSharedMemorySize, SMEM2_TOTAL);
    cudaFuncSetAttribute((const void*)hgemm_f16<3>,
                         cudaFuncAttributeMaxDynamicSharedMemorySize, SMEM2_TOTAL);

    const size_t sNC = (size_t)NSP * CH;
    const size_t sNN = (size_t)NSP * NSP;
    const size_t sW  = (size_t)CH * CH;

    dim3 tb(32, 8);
    dim3 tg(NSP / 32, CH / 32, BATCH);
    transpose_f16<<<tg, tb>>>(text, tT);
    transpose_f16<<<tg, tb>>>(img,  iT);
    convert_w<<<dim3(CH * CH / 256, 1, 4), 256>>>(w_tp, w_q, w_k, w_v, w);

    dim3 blk(256);
    dim3 grid_p (CH / 128, NSP / 128, BATCH);   // M=NSP, N=CH
    dim3 grid_v (NSP / 128, CH / 128, BATCH);   // M=CH,  N=NSP
    dim3 grid_s (NSP / 128, NSP / 128, BATCH);  // M=NSP, N=NSP

    // tfT[n][o] = text^T @ w_tp^T + b_tp[o]
    hgemm_f16<0><<<grid_p, blk, SMEM2_TOTAL>>>(
        tT, w, b_tp, nullptr, nullptr, tf, CH, CH, sNC, 0, sNC);
    // QT[n][o] = img^T @ w_q^T + b_q[o]
    hgemm_f16<0><<<grid_p, blk, SMEM2_TOTAL>>>(
        iT, w + sW, b_q, nullptr, nullptr, q, CH, CH, sNC, 0, sNC);
    // KT[n][o] = tfT @ w_k^T + b_k[o]
    hgemm_f16<0><<<grid_p, blk, SMEM2_TOTAL>>>(
        tf, w + 2 * sW, b_k, nullptr, nullptr, k, CH, CH, sNC, 0, sNC);
    // V[o][n] = w_v @ tf + b_v[o]
    hgemm_f16<1><<<grid_v, blk, SMEM2_TOTAL>>>(
        w + 3 * sW, tf, b_v, nullptr, nullptr, v, CH, NSP, 0, sNC, sNC);
    // S = scale * Q K^T
    hgemm_f16<2><<<grid_s, blk, SMEM2_TOTAL>>>(
        q, k, scale, nullptr, sp, nullptr, CH, NSP, sNC, sNC, sNN);
    // P = softmax(S)
    softmax_f16<<<BATCH * NSP, 256>>>(sp, p);
    // out = V P^T + img
    hgemm_f16<3><<<grid_v, blk, SMEM2_TOTAL>>>(
        v, p, nullptr, img, (float*)d_out, nullptr, NSP, NSP, sNC, sNN, sNC);
}

// round 12
// speedup vs baseline: 2.5034x; 1.0139x over previous
#include <cuda_runtime.h>
#include <cuda_fp16.h>
#include <cstdint>

#define NSP   2304
#define CH    512
#define BATCH 8

// ---- unified pure-f16 GEMM params (BK=64, 4 warps, warp tile 64x64) ----
#define BK2    64
#define PAD2   72                      // 64+8 halves; 144B stride, conflict-free
#define MAT2_B (128 * PAD2 * 2)        // 18432 bytes
#define STG2_B (2 * MAT2_B)
#define SMEM2_TOTAL (2 * STG2_B)       // 73728 bytes

// ---------------- scratch (device globals; no allocations) ------------------
__device__ __half g_tT  [(size_t)BATCH * NSP * CH];   // text^T [n][c] f16
__device__ __half g_iT  [(size_t)BATCH * NSP * CH];   // img^T  [n][c] f16
__device__ __half g_w   [(size_t)4 * CH * CH];        // w_tp,w_q,w_k,w_v f16
__device__ __half g_tfT [(size_t)BATCH * NSP * CH];   // tf^T [n][c]
__device__ __half g_qT  [(size_t)BATCH * NSP * CH];
__device__ __half g_kT  [(size_t)BATCH * NSP * CH];
__device__ __half g_v   [(size_t)BATCH * CH * NSP];   // V [c][n]
__device__ float  g_S   [(size_t)BATCH * NSP * NSP];
__device__ __half g_P   [(size_t)BATCH * NSP * NSP];

// ---------------- helpers ----------------------------------------------------
__device__ __forceinline__ uint32_t smem_u32(const void* p) {
    uint32_t a;
    asm("{ .reg .u64 t; cvta.to.shared.u64 t, %1; cvt.u32.u64 %0, t; }" : "=r"(a) : "l"(p));
    return a;
}
__device__ __forceinline__ void cp16(uint32_t saddr, const void* g) {
    asm volatile("cp.async.cg.shared.global [%0], [%1], 16;\n" :: "r"(saddr), "l"(g));
}
__device__ __forceinline__ void cp_commit() { asm volatile("cp.async.commit_group;\n"); }
template<int N> __device__ __forceinline__ void cp_wait() {
    asm volatile("cp.async.wait_group %0;\n" :: "n"(N));
}
__device__ __forceinline__ void ldsm4(unsigned (&r)[4], uint32_t addr) {
    asm volatile("ldmatrix.sync.aligned.m8n8.x4.shared.b16 {%0,%1,%2,%3}, [%4];"
        : "=r"(r[0]), "=r"(r[1]), "=r"(r[2]), "=r"(r[3]) : "r"(addr));
}
__device__ __forceinline__ void mma16816(float (&d)[4], const unsigned (&a)[4],
                                         unsigned b0, unsigned b1) {
    asm volatile(
        "mma.sync.aligned.m16n8k16.row.col.f32.f16.f16.f32 "
        "{%0,%1,%2,%3}, {%4,%5,%6,%7}, {%8,%9}, {%0,%1,%2,%3};\n"
        : "+f"(d[0]), "+f"(d[1]), "+f"(d[2]), "+f"(d[3])
        : "r"(a[0]), "r"(a[1]), "r"(a[2]), "r"(a[3]), "r"(b0), "r"(b1));
}

// ---------------- pre-pass: transpose fp32 [C][N] -> f16 [N][C] --------------
__global__ void transpose_f16(const float* __restrict__ in, __half* __restrict__ o)
{
    __shared__ float tile[32][33];
    const int bz = blockIdx.z;
    const float* I = in + (size_t)bz * CH * NSP;
    __half* H = o + (size_t)bz * NSP * CH;
    const int n0 = blockIdx.x * 32, c0 = blockIdx.y * 32;
    const int tx = threadIdx.x, ty = threadIdx.y;
#pragma unroll
    for (int j = 0; j < 32; j += 8)
        tile[ty + j][tx] = I[(size_t)(c0 + ty + j) * NSP + n0 + tx];
    __syncthreads();
#pragma unroll
    for (int j = 0; j < 32; j += 8)
        H[(size_t)(n0 + ty + j) * CH + c0 + tx] = __float2half_rn(tile[tx][ty + j]);
}

// ---------------- pre-pass: convert the four weight matrices to f16 ----------
__global__ void convert_w(const float* __restrict__ w0, const float* __restrict__ w1,
                          const float* __restrict__ w2, const float* __restrict__ w3,
                          __half* __restrict__ o)
{
    const int z = blockIdx.z;
    const float* w = (z == 0) ? w0 : (z == 1) ? w1 : (z == 2) ? w2 : w3;
    const int i = blockIdx.x * 256 + threadIdx.x;
    o[(size_t)z * CH * CH + i] = __float2half_rn(w[i]);
}

// ============================================================================
// Unified pure-f16 NT HGEMM. CTA tile 128x128, 4 warps (2x2), warp tile 64x64,
// BK=64 cp.async double-buffered, ldmatrix. ldsm:HMMA = 8:32 per k16 step.
//   Y[m][n] = sum_k A[m][k] * B[n][k]
// EPI 0: +bias[n] -> f16   | 1: +bias[m] -> f16
// EPI 2: *(*aux)  -> fp32  | 3: +res[m][n] -> fp32
// ============================================================================
template<int EPI>
__global__ __launch_bounds__(128, 2)
void hgemm_f16(const __half* __restrict__ Ag, const __half* __restrict__ Bg,
               const float* __restrict__ aux, const float* __restrict__ resg,
               float* __restrict__ Yfg, __half* __restrict__ Yhg,
               int K, int ldY, size_t strA, size_t strB, size_t strY)
{
    extern __shared__ char smem[];
    const uint32_t sb = smem_u32(smem);

    const int bz = blockIdx.z;
    const __half* A = Ag + strA * bz;
    const __half* B = Bg + strB * bz;
    const float* res = (EPI == 3) ? (resg + strY * bz) : nullptr;

    const int n0 = blockIdx.x * 128;
    const int m0 = blockIdx.y * 128;
    const int t    = threadIdx.x;
    const int lane = t & 31;
    const int warp = t >> 5;          // 0..3
    const int wm   = (warp & 1) * 64;
    const int wn   = (warp >> 1) * 64;
    const int grp  = lane >> 2;
    const int qid  = lane & 3;

    const uint32_t offA = (uint32_t)(wm + (lane & 15)) * (PAD2 * 2) + (lane >> 4) * 16;
    const uint32_t offB = (uint32_t)(wn + ((lane >> 4) & 1) * 8 + (lane & 7)) * (PAD2 * 2)
                        + ((lane >> 3) & 1) * 16;

    float acc[4][8][4];
#pragma unroll
    for (int mt = 0; mt < 4; mt++)
#pragma unroll
        for (int nt = 0; nt < 8; nt++)
#pragma unroll
            for (int r = 0; r < 4; r++) acc[mt][nt][r] = 0.f;

    auto load_chunk = [&](int c) {
        const int k0 = c * BK2;
        const uint32_t so = sb + (c & 1) * STG2_B;
#pragma unroll
        for (int i = 0; i < 8; i++) {           // A: 128 rows x 8 x 16B
            const int idx = t + 128 * i;
            const int kg = idx & 7, r = idx >> 3;
            cp16(so + r * (PAD2 * 2) + kg * 16,
                 &A[(size_t)(m0 + r) * K + k0 + kg * 8]);
        }
#pragma unroll
        for (int i = 0; i < 8; i++) {           // B
            const int idx = t + 128 * i;
            const int kg = idx & 7, r = idx >> 3;
            cp16(so + MAT2_B + r * (PAD2 * 2) + kg * 16,
                 &B[(size_t)(n0 + r) * K + k0 + kg * 8]);
        }
        cp_commit();
    };

    const int nch = K / BK2;
    load_chunk(0);
    if (nch > 1) load_chunk(1);

    for (int c = 0; c < nch; c++) {
        if (c + 1 < nch) cp_wait<1>(); else cp_wait<0>();
        __syncthreads();

        const uint32_t stg = sb + (c & 1) * STG2_B;

#pragma unroll
        for (int ks = 0; ks < 4; ks++) {
            const uint32_t kb2 = ks * 32;       // 16 halves = 32 bytes
            unsigned a[4][4];
#pragma unroll
            for (int mt = 0; mt < 4; mt++)
                ldsm4(a[mt], stg + offA + mt * 16 * (PAD2 * 2) + kb2);
#pragma unroll
            for (int np = 0; np < 4; np++) {
                unsigned b[4];
                ldsm4(b, stg + MAT2_B + offB + np * 16 * (PAD2 * 2) + kb2);
#pragma unroll
                for (int mt = 0; mt < 4; mt++) {
                    mma16816(acc[mt][2 * np],     a[mt], b[0], b[1]);
                    mma16816(acc[mt][2 * np + 1], a[mt], b[2], b[3]);
                }
            }
        }
        __syncthreads();
        if (c + 2 < nch) load_chunk(c + 2);
    }

    // ---- epilogue ----
    float* Yf  = (EPI >= 2) ? (Yfg + strY * bz) : nullptr;
    __half* Yh = (EPI < 2) ? (Yhg + strY * bz) : nullptr;
    const float sc = (EPI == 2) ? *aux : 0.f;

#pragma unroll
    for (int mt = 0; mt < 4; mt++)
#pragma unroll
        for (int r2 = 0; r2 < 2; r2++) {
            const int m = m0 + wm + mt * 16 + grp + 8 * r2;
            const float bvr = (EPI == 1) ? aux[m] : 0.f;
#pragma unroll
            for (int nt = 0; nt < 8; nt++) {
                const int n = n0 + wn + nt * 8 + qid * 2;
                const size_t off = (size_t)m * ldY + n;
                float v0 = acc[mt][nt][r2 * 2 + 0];
                float v1 = acc[mt][nt][r2 * 2 + 1];
                if (EPI == 0) { v0 += aux[n]; v1 += aux[n + 1]; }
                if (EPI == 1) { v0 += bvr;    v1 += bvr; }
                if (EPI == 2) { v0 *= sc;     v1 *= sc; }
                if (EPI == 3) { v0 += res[off]; v1 += res[off + 1]; }
                if (EPI >= 2) {
                    *(float2*)&Yf[off] = make_float2(v0, v1);
                } else {
                    *(__half2*)&Yh[off] =
                        __halves2half2(__float2half_rn(v0), __float2half_rn(v1));
                }
            }
        }
}

// ---------------- softmax over rows of S, emit f16 P -------------------------
__global__ void softmax_f16(const float* __restrict__ S, __half* __restrict__ Ph)
{
    __shared__ float red[256];
    const size_t ro = (size_t)blockIdx.x * NSP;
    const float* r = S + ro;
    const int t = threadIdx.x;

    float v[9];
    float mx = -1e30f;
#pragma unroll
    for (int i = 0; i < 9; i++) { v[i] = r[t + i * 256]; mx = fmaxf(mx, v[i]); }
    red[t] = mx;
    __syncthreads();
    for (int s = 128; s > 0; s >>= 1) {
        if (t < s) red[t] = fmaxf(red[t], red[t + s]);
        __syncthreads();
    }
    mx = red[0];
    __syncthreads();
    float sum = 0.f;
#pragma unroll
    for (int i = 0; i < 9; i++) { v[i] = __expf(v[i] - mx); sum += v[i]; }
    red[t] = sum;
    __syncthreads();
    for (int s = 128; s > 0; s >>= 1) {
        if (t < s) red[t] += red[t + s];
        __syncthreads();
    }
    const float inv = 1.0f / red[0];
#pragma unroll
    for (int i = 0; i < 9; i++)
        Ph[ro + t + i * 256] = __float2half_rn(v[i] * inv);
}

// ============================================================================
// Launch
// ============================================================================
extern "C" void kernel_launch(void* const* d_in, const int* in_sizes, int n_in,
                              void* d_out, int out_size)
{
    const float* img   = (const float*)d_in[0];
    const float* text  = (const float*)d_in[1];
    const float* w_tp  = (const float*)d_in[2];
    const float* b_tp  = (const float*)d_in[3];
    const float* w_q   = (const float*)d_in[4];
    const float* b_q   = (const float*)d_in[5];
    const float* w_k   = (const float*)d_in[6];
    const float* b_k   = (const float*)d_in[7];
    const float* w_v   = (const float*)d_in[8];
    const float* b_v   = (const float*)d_in[9];
    const float* scale = (const float*)d_in[10];

    __half *tT, *iT, *w, *tf, *q, *k, *v, *p;
    float* sp;
    cudaGetSymbolAddress((void**)&tT, g_tT);
    cudaGetSymbolAddress((void**)&iT, g_iT);
    cudaGetSymbolAddress((void**)&w,  g_w);
    cudaGetSymbolAddress((void**)&tf, g_tfT);
    cudaGetSymbolAddress((void**)&q,  g_qT);
    cudaGetSymbolAddress((void**)&k,  g_kT);
    cudaGetSymbolAddress((void**)&v,  g_v);
    cudaGetSymbolAddress((void**)&p,  g_P);
    cudaGetSymbolAddress((void**)&sp, g_S);

    cudaFuncSetAttribute((const void*)hgemm_f16<0>,
                         cudaFuncAttributeMaxDynamicSharedMemorySize, SMEM2_TOTAL);
    cudaFuncSetAttribute((const void*)hgemm_f16<1>,
                         cudaFuncAttributeMaxDynamicSharedMemorySize, SMEM2_TOTAL);
    cudaFuncSetAttribute((const void*)hgemm_f16<2>,
                         cudaFuncAttributeMaxDynamicSharedMemorySize, SMEM2_TOTAL);
    cudaFuncSetAttribute((const void*)hgemm_f16<3>,
                         cudaFuncAttributeMaxDynamicSharedMemorySize, SMEM2_TOTAL);

    const size_t sNC = (size_t)NSP * CH;
    const size_t sNN = (size_t)NSP * NSP;
    const size_t sW  = (size_t)CH * CH;

    dim3 tb(32, 8);
    dim3 tg(NSP / 32, CH / 32, BATCH);
    transpose_f16<<<tg, tb>>>(text, tT);
    transpose_f16<<<tg, tb>>>(img,  iT);
    convert_w<<<dim3(CH * CH / 256, 1, 4), 256>>>(w_tp, w_q, w_k, w_v, w);

    dim3 blk(128);
    dim3 grid_p (CH / 128, NSP / 128, BATCH);   // M=NSP, N=CH
    dim3 grid_v (NSP / 128, CH / 128, BATCH);   // M=CH,  N=NSP
    dim3 grid_s (NSP / 128, NSP / 128, BATCH);  // M=NSP, N=NSP

    // tfT[n][o] = text^T @ w_tp^T + b_tp[o]
    hgemm_f16<0><<<grid_p, blk, SMEM2_TOTAL>>>(
        tT, w, b_tp, nullptr, nullptr, tf, CH, CH, sNC, 0, sNC);
    // QT[n][o] = img^T @ w_q^T + b_q[o]
    hgemm_f16<0><<<grid_p, blk, SMEM2_TOTAL>>>(
        iT, w + sW, b_q, nullptr, nullptr, q, CH, CH, sNC, 0, sNC);
    // KT[n][o] = tfT @ w_k^T + b_k[o]
    hgemm_f16<0><<<grid_p, blk, SMEM2_TOTAL>>>(
        tf, w + 2 * sW, b_k, nullptr, nullptr, k, CH, CH, sNC, 0, sNC);
    // V[o][n] = w_v @ tf + b_v[o]
    hgemm_f16<1><<<grid_v, blk, SMEM2_TOTAL>>>(
        w + 3 * sW, tf, b_v, nullptr, nullptr, v, CH, NSP, 0, sNC, sNC);
    // S = scale * Q K^T
    hgemm_f16<2><<<grid_s, blk, SMEM2_TOTAL>>>(
        q, k, scale, nullptr, sp, nullptr, CH, NSP, sNC, sNC, sNN);
    // P = softmax(S)
    softmax_f16<<<BATCH * NSP, 256>>>(sp, p);
    // out = V P^T + img
    hgemm_f16<3><<<grid_v, blk, SMEM2_TOTAL>>>(
        v, p, nullptr, img, (float*)d_out, nullptr, NSP, NSP, sNC, sNN, sNC);
}

// round 13
// speedup vs baseline: 2.5425x; 1.0156x over previous
#include <cuda_runtime.h>
#include <cuda_fp16.h>
#include <cstdint>

#define NSP   2304
#define CH    512
#define BATCH 8

// ---- unified pure-f16 GEMM params (BK=64, 4 warps, warp tile 64x64) ----
#define BK2    64
#define PAD2   72                      // 64+8 halves; 144B stride, conflict-free
#define MAT2_B (128 * PAD2 * 2)        // 18432 bytes
#define STG2_B (2 * MAT2_B)
#define SMEM2_TOTAL (2 * STG2_B)       // 73728 bytes
#define S_NC  ((size_t)NSP * CH)
#define S_NN  ((size_t)NSP * NSP)
#define S_W   ((size_t)CH * CH)

// ---------------- scratch (device globals; no allocations) ------------------
__device__ __half g_tT  [(size_t)BATCH * NSP * CH];
__device__ __half g_iT  [(size_t)BATCH * NSP * CH];
__device__ __half g_w   [(size_t)4 * CH * CH];
__device__ __half g_tfT [(size_t)BATCH * NSP * CH];
__device__ __half g_qT  [(size_t)BATCH * NSP * CH];
__device__ __half g_kT  [(size_t)BATCH * NSP * CH];
__device__ __half g_v   [(size_t)BATCH * CH * NSP];
__device__ float  g_S   [(size_t)BATCH * NSP * NSP];
__device__ __half g_P   [(size_t)BATCH * NSP * NSP];

// ---------------- helpers ----------------------------------------------------
__device__ __forceinline__ uint32_t smem_u32(const void* p) {
    uint32_t a;
    asm("{ .reg .u64 t; cvta.to.shared.u64 t, %1; cvt.u32.u64 %0, t; }" : "=r"(a) : "l"(p));
    return a;
}
__device__ __forceinline__ void cp16(uint32_t saddr, const void* g) {
    asm volatile("cp.async.cg.shared.global [%0], [%1], 16;\n" :: "r"(saddr), "l"(g));
}
__device__ __forceinline__ void cp_commit() { asm volatile("cp.async.commit_group;\n"); }
template<int N> __device__ __forceinline__ void cp_wait() {
    asm volatile("cp.async.wait_group %0;\n" :: "n"(N));
}
__device__ __forceinline__ void ldsm4(unsigned (&r)[4], uint32_t addr) {
    asm volatile("ldmatrix.sync.aligned.m8n8.x4.shared.b16 {%0,%1,%2,%3}, [%4];"
        : "=r"(r[0]), "=r"(r[1]), "=r"(r[2]), "=r"(r[3]) : "r"(addr));
}
__device__ __forceinline__ void mma16816(float (&d)[4], const unsigned (&a)[4],
                                         unsigned b0, unsigned b1) {
    asm volatile(
        "mma.sync.aligned.m16n8k16.row.col.f32.f16.f16.f32 "
        "{%0,%1,%2,%3}, {%4,%5,%6,%7}, {%8,%9}, {%0,%1,%2,%3};\n"
        : "+f"(d[0]), "+f"(d[1]), "+f"(d[2]), "+f"(d[3])
        : "r"(a[0]), "r"(a[1]), "r"(a[2]), "r"(a[3]), "r"(b0), "r"(b1));
}

// ============================================================================
// Shared GEMM core: CTA 128x128, 4 warps (2x2), warp tile 64x64, BK=64,
// cp.async double-buffered, ldmatrix fragment loads. (R12 mainloop, verbatim.)
// ============================================================================
__device__ __forceinline__ void gemm_core(
    const __half* __restrict__ A, const __half* __restrict__ B,
    int K, int m0, int n0, uint32_t sb, int t,
    uint32_t offA, uint32_t offB, float (&acc)[4][8][4])
{
    auto load_chunk = [&](int c) {
        const int k0 = c * BK2;
        const uint32_t so = sb + (c & 1) * STG2_B;
#pragma unroll
        for (int i = 0; i < 8; i++) {
            const int idx = t + 128 * i;
            const int kg = idx & 7, r = idx >> 3;
            cp16(so + r * (PAD2 * 2) + kg * 16,
                 &A[(size_t)(m0 + r) * K + k0 + kg * 8]);
        }
#pragma unroll
        for (int i = 0; i < 8; i++) {
            const int idx = t + 128 * i;
            const int kg = idx & 7, r = idx >> 3;
            cp16(so + MAT2_B + r * (PAD2 * 2) + kg * 16,
                 &B[(size_t)(n0 + r) * K + k0 + kg * 8]);
        }
        cp_commit();
    };

    const int nch = K / BK2;
    load_chunk(0);
    if (nch > 1) load_chunk(1);

    for (int c = 0; c < nch; c++) {
        if (c + 1 < nch) cp_wait<1>(); else cp_wait<0>();
        __syncthreads();

        const uint32_t stg = sb + (c & 1) * STG2_B;
#pragma unroll
        for (int ks = 0; ks < 4; ks++) {
            const uint32_t kb2 = ks * 32;
            unsigned a[4][4];
#pragma unroll
            for (int mt = 0; mt < 4; mt++)
                ldsm4(a[mt], stg + offA + mt * 16 * (PAD2 * 2) + kb2);
#pragma unroll
            for (int np = 0; np < 4; np++) {
                unsigned b[4];
                ldsm4(b, stg + MAT2_B + offB + np * 16 * (PAD2 * 2) + kb2);
#pragma unroll
                for (int mt = 0; mt < 4; mt++) {
                    mma16816(acc[mt][2 * np],     a[mt], b[0], b[1]);
                    mma16816(acc[mt][2 * np + 1], a[mt], b[2], b[3]);
                }
            }
        }
        __syncthreads();
        if (c + 2 < nch) load_chunk(c + 2);
    }
}

// ---------------- lane mapping helpers ----------------------------------------
struct LaneMap {
    int lane, warp, wm, wn, grp, qid;
    uint32_t offA, offB;
};
__device__ __forceinline__ LaneMap lane_map(int t) {
    LaneMap L;
    L.lane = t & 31;
    L.warp = t >> 5;
    L.wm   = (L.warp & 1) * 64;
    L.wn   = (L.warp >> 1) * 64;
    L.grp  = L.lane >> 2;
    L.qid  = L.lane & 3;
    L.offA = (uint32_t)(L.wm + (L.lane & 15)) * (PAD2 * 2) + (L.lane >> 4) * 16;
    L.offB = (uint32_t)(L.wn + ((L.lane >> 4) & 1) * 8 + (L.lane & 7)) * (PAD2 * 2)
           + ((L.lane >> 3) & 1) * 16;
    return L;
}

// ---------------- f16 epilogue with bias (biasN: bias[n] else bias[m]) --------
__device__ __forceinline__ void epi_bias_f16(
    float (&acc)[4][8][4], const LaneMap& L, int m0, int n0, int ldY,
    const float* __restrict__ bias, bool biasN, __half* __restrict__ Y)
{
#pragma unroll
    for (int mt = 0; mt < 4; mt++)
#pragma unroll
        for (int r2 = 0; r2 < 2; r2++) {
            const int m = m0 + L.wm + mt * 16 + L.grp + 8 * r2;
            const float bvr = biasN ? 0.f : bias[m];
#pragma unroll
            for (int nt = 0; nt < 8; nt++) {
                const int n = n0 + L.wn + nt * 8 + L.qid * 2;
                float v0 = acc[mt][nt][r2 * 2 + 0];
                float v1 = acc[mt][nt][r2 * 2 + 1];
                if (biasN) { v0 += bias[n]; v1 += bias[n + 1]; }
                else       { v0 += bvr;     v1 += bvr; }
                *(__half2*)&Y[(size_t)m * ldY + n] =
                    __halves2half2(__float2half_rn(v0), __float2half_rn(v1));
            }
        }
}

// ============================================================================
// Merged tf + Q projection: z = 0..15, op = z>>3 (0: tf, 1: Q)
// ============================================================================
__global__ __launch_bounds__(128, 2)
void proj_tfq(const __half* __restrict__ tT, const __half* __restrict__ iT,
              const __half* __restrict__ w,
              const float* __restrict__ b_tp, const float* __restrict__ b_q,
              __half* __restrict__ tf, __half* __restrict__ q)
{
    extern __shared__ char smem[];
    const uint32_t sb = smem_u32(smem);
    const int t = threadIdx.x;
    const int z = blockIdx.z, op = z >> 3, bz = z & 7;

    const __half* A = (op ? iT : tT) + S_NC * bz;
    const __half* B = w + (size_t)op * S_W;
    const float* bias = op ? b_q : b_tp;
    __half* Y = (op ? q : tf) + S_NC * bz;

    const int n0 = blockIdx.x * 128;   // CH tiles (4)
    const int m0 = blockIdx.y * 128;   // NSP tiles (18)
    const LaneMap L = lane_map(t);

    float acc[4][8][4];
#pragma unroll
    for (int mt = 0; mt < 4; mt++)
#pragma unroll
        for (int nt = 0; nt < 8; nt++)
#pragma unroll
            for (int r = 0; r < 4; r++) acc[mt][nt][r] = 0.f;

    gemm_core(A, B, CH, m0, n0, sb, t, L.offA, L.offB, acc);
    epi_bias_f16(acc, L, m0, n0, CH, bias, true, Y);
}

// ============================================================================
// Merged K + V projection: grid.x = 144; bx<72 -> K proj, else V proj.
//   K: Y=kT[n][o] = tf @ w_k^T + b_k[o]   (M=NSP, N=CH, bias n, ldY=CH)
//   V: Y=v[o][n]  = w_v @ tf + b_v[o]     (M=CH, N=NSP, bias m, ldY=NSP)
// ============================================================================
__global__ __launch_bounds__(128, 2)
void proj_kv(const __half* __restrict__ tf,
             const __half* __restrict__ w_k, const __half* __restrict__ w_v,
             const float* __restrict__ b_k, const float* __restrict__ b_v,
             __half* __restrict__ kO, __half* __restrict__ vO)
{
    extern __shared__ char smem[];
    const uint32_t sb = smem_u32(smem);
    const int t = threadIdx.x;
    const int bz = blockIdx.z;
    const bool isV = blockIdx.x >= 72;
    const int bx = isV ? blockIdx.x - 72 : blockIdx.x;

    const __half* tfb = tf + S_NC * bz;
    const __half* A;
    const __half* B;
    const float* bias;
    __half* Y;
    int n0, m0, ldY;
    if (!isV) {
        n0 = (bx & 3) * 128;  m0 = (bx >> 2) * 128;    // (4 x, 18 y)
        A = tfb; B = w_k; bias = b_k; Y = kO + S_NC * bz; ldY = CH;
    } else {
        n0 = (bx % 18) * 128; m0 = (bx / 18) * 128;    // (18 x, 4 y)
        A = w_v; B = tfb; bias = b_v; Y = vO + S_NC * bz; ldY = NSP;
    }
    const LaneMap L = lane_map(t);

    float acc[4][8][4];
#pragma unroll
    for (int mt = 0; mt < 4; mt++)
#pragma unroll
        for (int nt = 0; nt < 8; nt++)
#pragma unroll
            for (int r = 0; r < 4; r++) acc[mt][nt][r] = 0.f;

    gemm_core(A, B, CH, m0, n0, sb, t, L.offA, L.offB, acc);
    epi_bias_f16(acc, L, m0, n0, ldY, bias, !isV, Y);
}

// ============================================================================
// S = scale * Q K^T  (fp32 out)
// ============================================================================
__global__ __launch_bounds__(128, 2)
void gemm_s(const __half* __restrict__ q, const __half* __restrict__ k,
            const float* __restrict__ scale, float* __restrict__ Sg)
{
    extern __shared__ char smem[];
    const uint32_t sb = smem_u32(smem);
    const int t = threadIdx.x;
    const int bz = blockIdx.z;
    const __half* A = q + S_NC * bz;
    const __half* B = k + S_NC * bz;
    float* Y = Sg + S_NN * bz;
    const int n0 = blockIdx.x * 128;
    const int m0 = blockIdx.y * 128;
    const LaneMap L = lane_map(t);

    float acc[4][8][4];
#pragma unroll
    for (int mt = 0; mt < 4; mt++)
#pragma unroll
        for (int nt = 0; nt < 8; nt++)
#pragma unroll
            for (int r = 0; r < 4; r++) acc[mt][nt][r] = 0.f;

    gemm_core(A, B, CH, m0, n0, sb, t, L.offA, L.offB, acc);

    const float sc = *scale;
#pragma unroll
    for (int mt = 0; mt < 4; mt++)
#pragma unroll
        for (int r2 = 0; r2 < 2; r2++) {
            const int m = m0 + L.wm + mt * 16 + L.grp + 8 * r2;
#pragma unroll
            for (int nt = 0; nt < 8; nt++) {
                const int n = n0 + L.wn + nt * 8 + L.qid * 2;
                *(float2*)&Y[(size_t)m * NSP + n] =
                    make_float2(acc[mt][nt][r2 * 2] * sc, acc[mt][nt][r2 * 2 + 1] * sc);
            }
        }
}

// ============================================================================
// out = V P^T + img  (fp32 out)
// ============================================================================
__global__ __launch_bounds__(128, 2)
void gemm_out(const __half* __restrict__ v, const __half* __restrict__ p,
              const float* __restrict__ img, float* __restrict__ out)
{
    extern __shared__ char smem[];
    const uint32_t sb = smem_u32(smem);
    const int t = threadIdx.x;
    const int bz = blockIdx.z;
    const __half* A = v + S_NC * bz;
    const __half* B = p + S_NN * bz;
    const float* res = img + S_NC * bz;
    float* Y = out + S_NC * bz;
    const int n0 = blockIdx.x * 128;
    const int m0 = blockIdx.y * 128;
    const LaneMap L = lane_map(t);

    float acc[4][8][4];
#pragma unroll
    for (int mt = 0; mt < 4; mt++)
#pragma unroll
        for (int nt = 0; nt < 8; nt++)
#pragma unroll
            for (int r = 0; r < 4; r++) acc[mt][nt][r] = 0.f;

    gemm_core(A, B, NSP, m0, n0, sb, t, L.offA, L.offB, acc);

#pragma unroll
    for (int mt = 0; mt < 4; mt++)
#pragma unroll
        for (int r2 = 0; r2 < 2; r2++) {
            const int m = m0 + L.wm + mt * 16 + L.grp + 8 * r2;
#pragma unroll
            for (int nt = 0; nt < 8; nt++) {
                const int n = n0 + L.wn + nt * 8 + L.qid * 2;
                const size_t off = (size_t)m * NSP + n;
                *(float2*)&Y[off] = make_float2(acc[mt][nt][r2 * 2] + res[off],
                                                acc[mt][nt][r2 * 2 + 1] + res[off + 1]);
            }
        }
}

// ---------------- merged pre-pass: transpose both text and img ----------------
__global__ void transpose2_f16(const float* __restrict__ text,
                               const float* __restrict__ img,
                               __half* __restrict__ tT, __half* __restrict__ iT)
{
    __shared__ float tile[32][33];
    const int z = blockIdx.z, op = z >> 3, bz = z & 7;
    const float* I = (op ? img : text) + (size_t)bz * CH * NSP;
    __half* H = (op ? iT : tT) + (size_t)bz * NSP * CH;
    const int n0 = blockIdx.x * 32, c0 = blockIdx.y * 32;
    const int tx = threadIdx.x, ty = threadIdx.y;
#pragma unroll
    for (int j = 0; j < 32; j += 8)
        tile[ty + j][tx] = I[(size_t)(c0 + ty + j) * NSP + n0 + tx];
    __syncthreads();
#pragma unroll
    for (int j = 0; j < 32; j += 8)
        H[(size_t)(n0 + ty + j) * CH + c0 + tx] = __float2half_rn(tile[tx][ty + j]);
}

__global__ void convert_w(const float* __restrict__ w0, const float* __restrict__ w1,
                          const float* __restrict__ w2, const float* __restrict__ w3,
                          __half* __restrict__ o)
{
    const int z = blockIdx.z;
    const float* w = (z == 0) ? w0 : (z == 1) ? w1 : (z == 2) ? w2 : w3;
    const int i = blockIdx.x * 256 + threadIdx.x;
    o[(size_t)z * CH * CH + i] = __float2half_rn(w[i]);
}

// ---------------- softmax over rows of S, emit f16 P -------------------------
__global__ void softmax_f16(const float* __restrict__ S, __half* __restrict__ Ph)
{
    __shared__ float red[256];
    const size_t ro = (size_t)blockIdx.x * NSP;
    const float* r = S + ro;
    const int t = threadIdx.x;

    float v[9];
    float mx = -1e30f;
#pragma unroll
    for (int i = 0; i < 9; i++) { v[i] = r[t + i * 256]; mx = fmaxf(mx, v[i]); }
    red[t] = mx;
    __syncthreads();
    for (int s = 128; s > 0; s >>= 1) {
        if (t < s) red[t] = fmaxf(red[t], red[t + s]);
        __syncthreads();
    }
    mx = red[0];
    __syncthreads();
    float sum = 0.f;
#pragma unroll
    for (int i = 0; i < 9; i++) { v[i] = __expf(v[i] - mx); sum += v[i]; }
    red[t] = sum;
    __syncthreads();
    for (int s = 128; s > 0; s >>= 1) {
        if (t < s) red[t] += red[t + s];
        __syncthreads();
    }
    const float inv = 1.0f / red[0];
#pragma unroll
    for (int i = 0; i < 9; i++)
        Ph[ro + t + i * 256] = __float2half_rn(v[i] * inv);
}

// ============================================================================
// Launch
// ============================================================================
extern "C" void kernel_launch(void* const* d_in, const int* in_sizes, int n_in,
                              void* d_out, int out_size)
{
    const float* img   = (const float*)d_in[0];
    const float* text  = (const float*)d_in[1];
    const float* w_tp  = (const float*)d_in[2];
    const float* b_tp  = (const float*)d_in[3];
    const float* w_q   = (const float*)d_in[4];
    const float* b_q   = (const float*)d_in[5];
    const float* w_k   = (const float*)d_in[6];
    const float* b_k   = (const float*)d_in[7];
    const float* w_v   = (const float*)d_in[8];
    const float* b_v   = (const float*)d_in[9];
    const float* scale = (const float*)d_in[10];

    __half *tT, *iT, *w, *tf, *q, *k, *v, *p;
    float* sp;
    cudaGetSymbolAddress((void**)&tT, g_tT);
    cudaGetSymbolAddress((void**)&iT, g_iT);
    cudaGetSymbolAddress((void**)&w,  g_w);
    cudaGetSymbolAddress((void**)&tf, g_tfT);
    cudaGetSymbolAddress((void**)&q,  g_qT);
    cudaGetSymbolAddress((void**)&k,  g_kT);
    cudaGetSymbolAddress((void**)&v,  g_v);
    cudaGetSymbolAddress((void**)&p,  g_P);
    cudaGetSymbolAddress((void**)&sp, g_S);

    cudaFuncSetAttribute((const void*)proj_tfq,
                         cudaFuncAttributeMaxDynamicSharedMemorySize, SMEM2_TOTAL);
    cudaFuncSetAttribute((const void*)proj_kv,
                         cudaFuncAttributeMaxDynamicSharedMemorySize, SMEM2_TOTAL);
    cudaFuncSetAttribute((const void*)gemm_s,
                         cudaFuncAttributeMaxDynamicSharedMemorySize, SMEM2_TOTAL);
    cudaFuncSetAttribute((const void*)gemm_out,
                         cudaFuncAttributeMaxDynamicSharedMemorySize, SMEM2_TOTAL);

    dim3 tb(32, 8);
    transpose2_f16<<<dim3(NSP / 32, CH / 32, 2 * BATCH), tb>>>(text, img, tT, iT);
    convert_w<<<dim3(CH * CH / 256, 1, 4), 256>>>(w_tp, w_q, w_k, w_v, w);

    dim3 blk(128);
    // tf + Q in one launch
    proj_tfq<<<dim3(CH / 128, NSP / 128, 2 * BATCH), blk, SMEM2_TOTAL>>>(
        tT, iT, w, b_tp, b_q, tf, q);
    // K + V in one launch
    proj_kv<<<dim3(144, 1, BATCH), blk, SMEM2_TOTAL>>>(
        tf, w + 2 * S_W, w + 3 * S_W, b_k, b_v, k, v);
    // S = scale * Q K^T
    gemm_s<<<dim3(NSP / 128, NSP / 128, BATCH), blk, SMEM2_TOTAL>>>(q, k, scale, sp);
    // P = softmax(S)
    softmax_f16<<<BATCH * NSP, 256>>>(sp, p);
    // out = V P^T + img
    gemm_out<<<dim3(NSP / 128, CH / 128, BATCH), blk, SMEM2_TOTAL>>>(
        v, p, img, (float*)d_out);
}